// round 1
// baseline (speedup 1.0000x reference)
#include <cuda_runtime.h>
#include <math.h>

// Problem constants
#define Bv 2
#define Nv 2048
#define Dv 1024
#define Hv 16
#define Dhv 64
#define Mrows (Bv * Nv)   // 4096

// ---------------------------------------------------------------------------
// Scratch (static __device__ arrays: the sanctioned alloc-free workaround)
// ---------------------------------------------------------------------------
__device__ float g_Q[Mrows * Dv];
__device__ float g_K[Mrows * Dv];
__device__ float g_V[Mrows * Dv];
__device__ float g_O[Mrows * Dv];
__device__ float g_qn[Bv * Hv * Nv];
__device__ float g_kn[Bv * Hv * Nv];

// ---------------------------------------------------------------------------
// Fast math helpers (approx MUFU ops; rel err ~2^-22, fine vs 1e-3 gate)
// ---------------------------------------------------------------------------
__device__ __forceinline__ float f_lg2(float x) { float r; asm("lg2.approx.f32 %0, %1;" : "=f"(r) : "f"(x)); return r; }
__device__ __forceinline__ float f_ex2(float x) { float r; asm("ex2.approx.f32 %0, %1;" : "=f"(r) : "f"(x)); return r; }
__device__ __forceinline__ float f_sqrt(float x){ float r; asm("sqrt.approx.f32 %0, %1;" : "=f"(r) : "f"(x)); return r; }

// Swizzled transposed-tile index: element (k-index d, row/col c) of a 64-wide
// tile stored d-major. 16B-chunk XOR swizzle keeps both the staging stores
// (<=2-way) and the compute-phase v4 loads (conflict-free) cheap.
#define SW(d, c) (((d) << 6) + ((((((c) >> 2) ^ (((d) >> 2) & 15)) << 2)) | ((c) & 3)))

// ---------------------------------------------------------------------------
// SGEMM: C[4096,1024] = A[4096,1024] @ W[1024,1024]^T   (both row-major, NT)
// 128x128x16 tiles, 256 threads, 8x8 microtile.
// ---------------------------------------------------------------------------
__device__ __forceinline__ void sgemm_body(const float* __restrict__ A,
                                           const float* __restrict__ W,
                                           float* __restrict__ C) {
    __shared__ __align__(16) float As[16][132];
    __shared__ __align__(16) float Bs[16][132];
    const int bm = blockIdx.y * 128;
    const int bn = blockIdx.x * 128;
    const int t  = threadIdx.x;
    const int tx = t & 15, ty = t >> 4;

    float acc[8][8];
#pragma unroll
    for (int i = 0; i < 8; i++)
#pragma unroll
        for (int j = 0; j < 8; j++) acc[i][j] = 0.0f;

    for (int k0 = 0; k0 < 1024; k0 += 16) {
#pragma unroll
        for (int u = 0; u < 2; u++) {
            int id  = t + u * 256;
            int row = id >> 2;
            int kc  = (id & 3) << 2;
            float4 av = *(const float4*)(A + (size_t)(bm + row) * 1024 + k0 + kc);
            As[kc + 0][row] = av.x; As[kc + 1][row] = av.y;
            As[kc + 2][row] = av.z; As[kc + 3][row] = av.w;
            float4 bv = *(const float4*)(W + (size_t)(bn + row) * 1024 + k0 + kc);
            Bs[kc + 0][row] = bv.x; Bs[kc + 1][row] = bv.y;
            Bs[kc + 2][row] = bv.z; Bs[kc + 3][row] = bv.w;
        }
        __syncthreads();
#pragma unroll
        for (int kk = 0; kk < 16; kk++) {
            float a[8], b[8];
            *(float4*)(a)     = *(const float4*)&As[kk][ty * 4];
            *(float4*)(a + 4) = *(const float4*)&As[kk][64 + ty * 4];
            *(float4*)(b)     = *(const float4*)&Bs[kk][tx * 4];
            *(float4*)(b + 4) = *(const float4*)&Bs[kk][64 + tx * 4];
#pragma unroll
            for (int i = 0; i < 8; i++)
#pragma unroll
                for (int j = 0; j < 8; j++)
                    acc[i][j] = fmaf(a[i], b[j], acc[i][j]);
        }
        __syncthreads();
    }

#pragma unroll
    for (int ih = 0; ih < 2; ih++)
#pragma unroll
        for (int i = 0; i < 4; i++) {
            int r = bm + ih * 64 + ty * 4 + i;
#pragma unroll
            for (int jh = 0; jh < 2; jh++) {
                float4 v = make_float4(acc[ih * 4 + i][jh * 4 + 0],
                                       acc[ih * 4 + i][jh * 4 + 1],
                                       acc[ih * 4 + i][jh * 4 + 2],
                                       acc[ih * 4 + i][jh * 4 + 3]);
                *(float4*)(C + (size_t)r * 1024 + bn + jh * 64 + tx * 4) = v;
            }
        }
}

__global__ __launch_bounds__(256, 2)
void proj_qkv_kernel(const float* __restrict__ x,
                     const float* __restrict__ Wq,
                     const float* __restrict__ Wk,
                     const float* __restrict__ Wv) {
    const float* W; float* Cout;
    if (blockIdx.z == 0)      { W = Wq; Cout = g_Q; }
    else if (blockIdx.z == 1) { W = Wk; Cout = g_K; }
    else                      { W = Wv; Cout = g_V; }
    sgemm_body(x, W, Cout);
}

__global__ __launch_bounds__(256, 2)
void out_proj_kernel(const float* __restrict__ Wo, float* __restrict__ out) {
    sgemm_body(g_O, Wo, out);
}

// ---------------------------------------------------------------------------
// Per-(b,h,n) squared norms of q and k. One warp per row-head.
// Output layout [b][h][n] for coalesced attention access.
// ---------------------------------------------------------------------------
__global__ void norms_kernel() {
    int gid  = blockIdx.x * (blockDim.x >> 5) + (threadIdx.x >> 5);
    int lane = threadIdx.x & 31;
    const int total = 2 * Mrows * Hv;   // 131072
    if (gid >= total) return;
    int which = gid >> 16;              // 0 = Q, 1 = K   (65536 each)
    int rem   = gid & 65535;
    int row   = rem >> 4;               // b*N + n, 0..4095
    int h     = rem & 15;
    const float* src = which ? g_K : g_Q;
    const float* p = src + (size_t)row * Dv + h * Dhv;
    float s = 0.0f;
#pragma unroll
    for (int i = lane; i < Dhv; i += 32) { float v = p[i]; s = fmaf(v, v, s); }
#pragma unroll
    for (int o = 16; o; o >>= 1) s += __shfl_xor_sync(0xffffffffu, s, o);
    if (lane == 0) {
        int b = row >> 11, n = row & 2047;
        float* dst = which ? g_kn : g_qn;
        dst[((b << 4) + h) * Nv + n] = s;
    }
}

// ---------------------------------------------------------------------------
// Fused hyperbolic flash attention, fp32. 64x64 tiles, 256 threads.
// grid = (32 query tiles [reversed for load balance], 32 = B*H)
// ---------------------------------------------------------------------------
__global__ __launch_bounds__(256, 2)
void attn_kernel(const float* __restrict__ lc_p, const float* __restrict__ lb_p) {
    extern __shared__ float smem[];
    float* Qs = smem;               // 4096 floats, transposed+swizzled
    float* Ks = smem + 4096;        // transposed+swizzled
    float* Vs = smem + 8192;        // natural [kk][d]
    float* Ps = smem + 12288;       // transposed+swizzled

    const int bh = blockIdx.y;
    const int b  = bh >> 4, h = bh & 15;
    const int qt = (int)gridDim.x - 1 - (int)blockIdx.x;   // long blocks first
    const int t  = threadIdx.x;
    const int tx = t & 15, ty = t >> 4;

    const float cc = log1pf(expf(*lc_p));            // softplus(log_c)
    const float bb = log1pf(expf(*lb_p)) + 0.5f;     // softplus(log_beta)+0.5
    const float L2E = 1.4426950408889634f;

    // ---- stage Q tile (transposed+swizzled) ----
    const float* Qbase = g_Q + ((size_t)(b * Nv + qt * 64)) * Dv + h * Dhv;
#pragma unroll
    for (int u = 0; u < 4; u++) {
        int id  = t + u * 256;
        int row = id >> 4;
        int d0  = (id & 15) << 2;
        float4 qv = *(const float4*)(Qbase + (size_t)row * Dv + d0);
        Qs[SW(d0 + 0, row)] = qv.x; Qs[SW(d0 + 1, row)] = qv.y;
        Qs[SW(d0 + 2, row)] = qv.z; Qs[SW(d0 + 3, row)] = qv.w;
    }

    // qn for my 4 rows
    float qnr[4];
    const float* qnp = g_qn + (size_t)bh * Nv + qt * 64;
#pragma unroll
    for (int i = 0; i < 4; i++) qnr[i] = qnp[ty * 4 + i];

    float m_i[4], l_i[4], acc[4][4];
#pragma unroll
    for (int i = 0; i < 4; i++) {
        m_i[i] = -1e30f; l_i[i] = 0.0f;
#pragma unroll
        for (int j = 0; j < 4; j++) acc[i][j] = 0.0f;
    }

    const float* Kbase0 = g_K + ((size_t)b * Nv) * Dv + h * Dhv;
    const float* Vbase0 = g_V + ((size_t)b * Nv) * Dv + h * Dhv;
    const float* knp    = g_kn + (size_t)bh * Nv;

    for (int kt = 0; kt <= qt; kt++) {
        __syncthreads();   // prior S/AV reads of Ks/Vs/Ps complete
        const float* Kb = Kbase0 + (size_t)kt * 64 * Dv;
        const float* Vb = Vbase0 + (size_t)kt * 64 * Dv;
#pragma unroll
        for (int u = 0; u < 4; u++) {
            int id  = t + u * 256;
            int row = id >> 4;
            int d0  = (id & 15) << 2;
            float4 kv = *(const float4*)(Kb + (size_t)row * Dv + d0);
            Ks[SW(d0 + 0, row)] = kv.x; Ks[SW(d0 + 1, row)] = kv.y;
            Ks[SW(d0 + 2, row)] = kv.z; Ks[SW(d0 + 3, row)] = kv.w;
            float4 vv = *(const float4*)(Vb + (size_t)row * Dv + d0);
            *(float4*)&Vs[(row << 6) + d0] = vv;
        }
        __syncthreads();

        float4 kn4 = *(const float4*)(knp + kt * 64 + tx * 4);
        const float knv[4] = { kn4.x, kn4.y, kn4.z, kn4.w };

        // ---- S = Q K^T (64-deep dot products) ----
        float s[4][4];
#pragma unroll
        for (int i = 0; i < 4; i++)
#pragma unroll
            for (int j = 0; j < 4; j++) s[i][j] = 0.0f;
#pragma unroll 8
        for (int d = 0; d < 64; d++) {
            float4 qv = *(const float4*)&Qs[(d << 6) + ((ty ^ ((d >> 2) & 15)) << 2)];
            float4 kv = *(const float4*)&Ks[(d << 6) + ((tx ^ ((d >> 2) & 15)) << 2)];
            s[0][0] = fmaf(qv.x, kv.x, s[0][0]); s[0][1] = fmaf(qv.x, kv.y, s[0][1]);
            s[0][2] = fmaf(qv.x, kv.z, s[0][2]); s[0][3] = fmaf(qv.x, kv.w, s[0][3]);
            s[1][0] = fmaf(qv.y, kv.x, s[1][0]); s[1][1] = fmaf(qv.y, kv.y, s[1][1]);
            s[1][2] = fmaf(qv.y, kv.z, s[1][2]); s[1][3] = fmaf(qv.y, kv.w, s[1][3]);
            s[2][0] = fmaf(qv.z, kv.x, s[2][0]); s[2][1] = fmaf(qv.z, kv.y, s[2][1]);
            s[2][2] = fmaf(qv.z, kv.z, s[2][2]); s[2][3] = fmaf(qv.z, kv.w, s[2][3]);
            s[3][0] = fmaf(qv.w, kv.x, s[3][0]); s[3][1] = fmaf(qv.w, kv.y, s[3][1]);
            s[3][2] = fmaf(qv.w, kv.z, s[3][2]); s[3][3] = fmaf(qv.w, kv.w, s[3][3]);
        }

        // ---- hyperbolic distance -> scores ----
#pragma unroll
        for (int i = 0; i < 4; i++)
#pragma unroll
            for (int j = 0; j < 4; j++) {
                float da = fmaxf(qnr[i] - 2.0f * s[i][j] + knv[j], 0.0f) + 1e-8f;
                float ns = qnr[i] + knv[j];
                float dist;
                if (da > 4.0f) {
                    // asymptotic branch (dominant): log(sqrt(da)) = 0.5*ln(da)
                    dist = 0.693f + 0.34657359f * f_lg2(da) + cc * ns * 0.25f;
                } else {
                    float ed = f_sqrt(da);
                    if (ed < 0.1f) {
                        float cn = cc * ns;
                        dist = ed * (1.0f + 0.5f * cn + 0.125f * cn * cn);
                    } else if (ed > 2.0f) {
                        dist = 0.693f + 0.6931472f * f_lg2(ed + 1e-8f) + cc * ns * 0.25f;
                    } else {
                        dist = ed * f_sqrt(1.0f + cc * ns);
                    }
                }
                s[i][j] = -bb * dist;
            }

        if (kt == qt) {   // diagonal tile causal mask
#pragma unroll
            for (int i = 0; i < 4; i++)
#pragma unroll
                for (int j = 0; j < 4; j++)
                    if (4 * tx + j > 4 * ty + i) s[i][j] = -1e30f;
        }

        // ---- online softmax update ----
#pragma unroll
        for (int i = 0; i < 4; i++) {
            float tm = fmaxf(fmaxf(s[i][0], s[i][1]), fmaxf(s[i][2], s[i][3]));
            tm = fmaxf(tm, __shfl_xor_sync(0xffffffffu, tm, 1));
            tm = fmaxf(tm, __shfl_xor_sync(0xffffffffu, tm, 2));
            tm = fmaxf(tm, __shfl_xor_sync(0xffffffffu, tm, 4));
            tm = fmaxf(tm, __shfl_xor_sync(0xffffffffu, tm, 8));
            float mn   = fmaxf(m_i[i], tm);
            float corr = f_ex2((m_i[i] - mn) * L2E);
            m_i[i] = mn;
            float rs = 0.0f;
#pragma unroll
            for (int j = 0; j < 4; j++) {
                float p = f_ex2((s[i][j] - mn) * L2E);
                s[i][j] = p; rs += p;
            }
            rs += __shfl_xor_sync(0xffffffffu, rs, 1);
            rs += __shfl_xor_sync(0xffffffffu, rs, 2);
            rs += __shfl_xor_sync(0xffffffffu, rs, 4);
            rs += __shfl_xor_sync(0xffffffffu, rs, 8);
            l_i[i] = l_i[i] * corr + rs;
#pragma unroll
            for (int j = 0; j < 4; j++) acc[i][j] *= corr;
        }

        // ---- stage P transposed (Ps[c][r], swizzled) ----
#pragma unroll
        for (int j = 0; j < 4; j++) {
            int c = 4 * tx + j;
            *(float4*)&Ps[(c << 6) + ((ty ^ tx) << 2)] =
                make_float4(s[0][j], s[1][j], s[2][j], s[3][j]);
        }
        __syncthreads();

        // ---- acc += P V ----
#pragma unroll 8
        for (int kk = 0; kk < 64; kk++) {
            float4 pv = *(const float4*)&Ps[(kk << 6) + ((ty ^ (kk >> 2)) << 2)];
            float4 vv = *(const float4*)&Vs[(kk << 6) + (tx << 2)];
            acc[0][0] = fmaf(pv.x, vv.x, acc[0][0]); acc[0][1] = fmaf(pv.x, vv.y, acc[0][1]);
            acc[0][2] = fmaf(pv.x, vv.z, acc[0][2]); acc[0][3] = fmaf(pv.x, vv.w, acc[0][3]);
            acc[1][0] = fmaf(pv.y, vv.x, acc[1][0]); acc[1][1] = fmaf(pv.y, vv.y, acc[1][1]);
            acc[1][2] = fmaf(pv.y, vv.z, acc[1][2]); acc[1][3] = fmaf(pv.y, vv.w, acc[1][3]);
            acc[2][0] = fmaf(pv.z, vv.x, acc[2][0]); acc[2][1] = fmaf(pv.z, vv.y, acc[2][1]);
            acc[2][2] = fmaf(pv.z, vv.z, acc[2][2]); acc[2][3] = fmaf(pv.z, vv.w, acc[2][3]);
            acc[3][0] = fmaf(pv.w, vv.x, acc[3][0]); acc[3][1] = fmaf(pv.w, vv.y, acc[3][1]);
            acc[3][2] = fmaf(pv.w, vv.z, acc[3][2]); acc[3][3] = fmaf(pv.w, vv.w, acc[3][3]);
        }
    }

    // ---- epilogue: O = acc / l ----
    float* Ob = g_O + ((size_t)(b * Nv + qt * 64)) * Dv + h * Dhv;
#pragma unroll
    for (int i = 0; i < 4; i++) {
        float inv = 1.0f / l_i[i];
        *(float4*)(Ob + (size_t)(ty * 4 + i) * Dv + tx * 4) =
            make_float4(acc[i][0] * inv, acc[i][1] * inv,
                        acc[i][2] * inv, acc[i][3] * inv);
    }
}

// ---------------------------------------------------------------------------
// Launch
// ---------------------------------------------------------------------------
extern "C" void kernel_launch(void* const* d_in, const int* in_sizes, int n_in,
                              void* d_out, int out_size) {
    const float* x  = (const float*)d_in[0];
    const float* Wq = (const float*)d_in[1];
    const float* Wk = (const float*)d_in[2];
    const float* Wv = (const float*)d_in[3];
    const float* Wo = (const float*)d_in[4];
    const float* lc = (const float*)d_in[5];
    const float* lb = (const float*)d_in[6];
    float* out = (float*)d_out;

    // 1) QKV projections (fused over grid.z)
    dim3 gproj(1024 / 128, Mrows / 128, 3);
    proj_qkv_kernel<<<gproj, 256>>>(x, Wq, Wk, Wv);

    // 2) per-(b,h,n) squared norms
    norms_kernel<<<(2 * Mrows * Hv) / 8, 256>>>();

    // 3) fused hyperbolic flash attention
    const int smem_bytes = 4 * 4096 * (int)sizeof(float);   // 64 KB dynamic
    cudaFuncSetAttribute(attn_kernel, cudaFuncAttributeMaxDynamicSharedMemorySize,
                         smem_bytes);
    attn_kernel<<<dim3(Nv / 64, Bv * Hv), 256, smem_bytes>>>(lc, lb);

    // 4) output projection straight into d_out
    out_proj_kernel<<<dim3(1024 / 128, Mrows / 128), 256>>>(Wo, out);
}

// round 3
// speedup vs baseline: 1.5337x; 1.5337x over previous
#include <cuda_runtime.h>
#include <math.h>
#include <stdint.h>

// Problem constants
#define Bv 2
#define Nv 2048
#define Dv 1024
#define Hv 16
#define Dhv 64
#define Mrows (Bv * Nv)   // 4096

// ---------------------------------------------------------------------------
// Scratch
// ---------------------------------------------------------------------------
__device__ float g_Q[Mrows * Dv];
__device__ float g_K[Mrows * Dv];
__device__ float g_V[Mrows * Dv];
__device__ float g_O[Mrows * Dv];
__device__ float g_qn[Bv * Hv * Nv];
__device__ float g_kn[Bv * Hv * Nv];

// ---------------------------------------------------------------------------
// Helpers (plain-sm_100-safe PTX only: ldmatrix / mma.sync / cvt.bf16x2)
// ---------------------------------------------------------------------------
__device__ __forceinline__ uint32_t smem_u32(const void* p) {
    uint32_t a;
    asm("{ .reg .u64 t; cvta.to.shared.u64 t, %1; cvt.u32.u64 %0, t; }" : "=r"(a) : "l"(p));
    return a;
}

#define LDSM4(r0, r1, r2, r3, addr) \
    asm volatile("ldmatrix.sync.aligned.m8n8.x4.shared.b16 {%0,%1,%2,%3}, [%4];" \
        : "=r"(r0), "=r"(r1), "=r"(r2), "=r"(r3) : "r"(addr))

__device__ __forceinline__ void mma_bf16(float* d, const uint32_t* a, uint32_t b0, uint32_t b1) {
    asm volatile("mma.sync.aligned.m16n8k16.row.col.f32.bf16.bf16.f32 "
        "{%0,%1,%2,%3}, {%4,%5,%6,%7}, {%8,%9}, {%0,%1,%2,%3};"
        : "+f"(d[0]), "+f"(d[1]), "+f"(d[2]), "+f"(d[3])
        : "r"(a[0]), "r"(a[1]), "r"(a[2]), "r"(a[3]), "r"(b0), "r"(b1));
}

// fp32 float4 -> hi bf16x2 pair + lo bf16x2 pair, stored as 8B each.
// lo = x - f32(bf16(x)) is exact in fp32; dropped lo*lo term ~2^-16 relative.
__device__ __forceinline__ void split_sts8(float4 v, uint32_t hi_addr, uint32_t lo_addr) {
    uint32_t h01, h23, l01, l23;
    asm("cvt.rn.bf16x2.f32 %0, %1, %2;" : "=r"(h01) : "f"(v.y), "f"(v.x));
    asm("cvt.rn.bf16x2.f32 %0, %1, %2;" : "=r"(h23) : "f"(v.w), "f"(v.z));
    float xl = v.x - __uint_as_float(h01 << 16);
    float yl = v.y - __uint_as_float(h01 & 0xffff0000u);
    float zl = v.z - __uint_as_float(h23 << 16);
    float wl = v.w - __uint_as_float(h23 & 0xffff0000u);
    asm("cvt.rn.bf16x2.f32 %0, %1, %2;" : "=r"(l01) : "f"(yl), "f"(xl));
    asm("cvt.rn.bf16x2.f32 %0, %1, %2;" : "=r"(l23) : "f"(wl), "f"(zl));
    asm volatile("st.shared.v2.b32 [%0], {%1,%2};" :: "r"(hi_addr), "r"(h01), "r"(h23) : "memory");
    asm volatile("st.shared.v2.b32 [%0], {%1,%2};" :: "r"(lo_addr), "r"(l01), "r"(l23) : "memory");
}

// ---------------------------------------------------------------------------
// 3xBF16 mma.sync GEMM: C[.,1024] = A @ W^T, CTA tile 128x128, K=1024.
// 256 thr, warp tile 64x32. k-chunk 64 (128B bf16 rows, SW128 swizzle).
// smem: Ah | Al | Wh | Wl, 16KB each = 64KB single buffer, 2 CTAs/SM.
// ---------------------------------------------------------------------------
#define GSMEM_BYTES (65536 + 128)

__device__ void gemm3_body(const float* __restrict__ A, const float* __restrict__ W,
                           float* __restrict__ C) {
    extern __shared__ char sm_raw[];
    char* sm = (char*)(((uintptr_t)sm_raw + 127) & ~(uintptr_t)127);
    const uint32_t SB = smem_u32(sm);
    const uint32_t AH = SB, ALo = SB + 16384, WH = SB + 32768, WLo = SB + 49152;

    const int t  = threadIdx.x;
    const int L  = t & 31;
    const int wid = t >> 5;
    const int wm = wid >> 2;        // 0..1 : row base wm*64
    const int wn = wid & 3;         // 0..3 : col base wn*32
    const int m0 = blockIdx.y * 128;
    const int n0 = blockIdx.x * 128;

    // staging geometry: f4 index = t + 256u -> row = (t>>4)+16u, c = t&15
    const int srow = t >> 4, sc = t & 15;
    const float* pA = A + (size_t)(m0 + srow) * 1024 + sc * 4;
    const float* pW = W + (size_t)(n0 + srow) * 1024 + sc * 4;
    const uint32_t sts0 = (uint32_t)(srow * 128 + (((sc >> 1) ^ (srow & 7)) << 4) + (sc & 1) * 8);

    // ldmatrix lane geometry (SW128: 16B chunk c at row r -> chunk c^(r&7))
    const uint32_t aBase = AH + (uint32_t)((wm * 64 + (L & 15)) * 128);
    const uint32_t bBase = WH + (uint32_t)((wn * 32 + ((L >> 4) & 1) * 8 + (L & 7)) * 128);
    uint32_t aXor[4], bXor[4];
#pragma unroll
    for (int js = 0; js < 4; js++) {
        aXor[js] = (uint32_t)((((js * 2 + (L >> 4)) ^ (L & 7)) << 4));
        bXor[js] = (uint32_t)((((js * 2 + ((L >> 3) & 1)) ^ (L & 7)) << 4));
    }

    float acc[4][4][4];
#pragma unroll
    for (int i = 0; i < 4; i++)
#pragma unroll
        for (int j = 0; j < 4; j++)
#pragma unroll
            for (int r = 0; r < 4; r++) acc[i][j][r] = 0.0f;

#pragma unroll 1
    for (int k = 0; k < 16; k++) {
        const int kb = k * 64;
        // ---- stage half 0 (rows 0..63 of both tiles) ----
        float4 av[4], wv[4];
#pragma unroll
        for (int u = 0; u < 4; u++) {
            av[u] = *(const float4*)(pA + (size_t)u * 16384 + kb);
            wv[u] = *(const float4*)(pW + (size_t)u * 16384 + kb);
        }
        __syncthreads();   // previous chunk's mma reads complete
#pragma unroll
        for (int u = 0; u < 4; u++) {
            uint32_t off = sts0 + u * 2048;
            split_sts8(av[u], AH + off, ALo + off);
            split_sts8(wv[u], WH + off, WLo + off);
        }
        // ---- stage half 1 (rows 64..127) ----
#pragma unroll
        for (int u = 0; u < 4; u++) {
            av[u] = *(const float4*)(pA + (size_t)(u + 4) * 16384 + kb);
            wv[u] = *(const float4*)(pW + (size_t)(u + 4) * 16384 + kb);
        }
#pragma unroll
        for (int u = 0; u < 4; u++) {
            uint32_t off = sts0 + (u + 4) * 2048;
            split_sts8(av[u], AH + off, ALo + off);
            split_sts8(wv[u], WH + off, WLo + off);
        }
        __syncthreads();

        // ---- compute: 4 k16-steps, 3 products each ----
#pragma unroll
        for (int js = 0; js < 4; js++) {
            uint32_t ah[4][4], al[4][4];
#pragma unroll
            for (int i = 0; i < 4; i++) {
                LDSM4(ah[i][0], ah[i][1], ah[i][2], ah[i][3], aBase + i * 2048 + aXor[js]);
                LDSM4(al[i][0], al[i][1], al[i][2], al[i][3], aBase + 16384 + i * 2048 + aXor[js]);
            }
#pragma unroll
            for (int jp = 0; jp < 2; jp++) {
                uint32_t bh[4], bl[4];
                LDSM4(bh[0], bh[1], bh[2], bh[3], bBase + jp * 2048 + bXor[js]);
                LDSM4(bl[0], bl[1], bl[2], bl[3], bBase + 16384 + jp * 2048 + bXor[js]);
#pragma unroll
                for (int i = 0; i < 4; i++) {
                    mma_bf16(acc[i][jp * 2],     ah[i], bh[0], bh[1]);
                    mma_bf16(acc[i][jp * 2],     ah[i], bl[0], bl[1]);
                    mma_bf16(acc[i][jp * 2],     al[i], bh[0], bh[1]);
                    mma_bf16(acc[i][jp * 2 + 1], ah[i], bh[2], bh[3]);
                    mma_bf16(acc[i][jp * 2 + 1], ah[i], bl[2], bl[3]);
                    mma_bf16(acc[i][jp * 2 + 1], al[i], bh[2], bh[3]);
                }
            }
        }
    }

    // ---- epilogue: fragment -> GMEM (8B stores, 32B-coalesced per 4 lanes) ----
    const int rb = m0 + wm * 64 + (L >> 2);
    const int cb = n0 + wn * 32 + (L & 3) * 2;
#pragma unroll
    for (int i = 0; i < 4; i++)
#pragma unroll
        for (int j = 0; j < 4; j++) {
            const int r = rb + i * 16, cx = cb + j * 8;
            *(float2*)(C + (size_t)r * 1024 + cx)       = make_float2(acc[i][j][0], acc[i][j][1]);
            *(float2*)(C + (size_t)(r + 8) * 1024 + cx) = make_float2(acc[i][j][2], acc[i][j][3]);
        }
}

__global__ __launch_bounds__(256, 2)
void proj_qkv_mma(const float* __restrict__ x, const float* __restrict__ Wq,
                  const float* __restrict__ Wk, const float* __restrict__ Wv) {
    const float* W; float* C;
    if (blockIdx.z == 0)      { W = Wq; C = g_Q; }
    else if (blockIdx.z == 1) { W = Wk; C = g_K; }
    else                      { W = Wv; C = g_V; }
    gemm3_body(x, W, C);
}

__global__ __launch_bounds__(256, 2)
void out_proj_mma(const float* __restrict__ Wo, float* __restrict__ out) {
    gemm3_body(g_O, Wo, out);
}

// ---------------------------------------------------------------------------
// Per-(b,h,n) squared norms
// ---------------------------------------------------------------------------
__global__ void norms_kernel() {
    int gid  = blockIdx.x * (blockDim.x >> 5) + (threadIdx.x >> 5);
    int lane = threadIdx.x & 31;
    const int total = 2 * Mrows * Hv;
    if (gid >= total) return;
    int which = gid >> 16;
    int rem   = gid & 65535;
    int row   = rem >> 4;
    int h     = rem & 15;
    const float* src = which ? g_K : g_Q;
    const float* p = src + (size_t)row * Dv + h * Dhv;
    float s = 0.0f;
#pragma unroll
    for (int i = lane; i < Dhv; i += 32) { float v = p[i]; s = fmaf(v, v, s); }
#pragma unroll
    for (int o = 16; o; o >>= 1) s += __shfl_xor_sync(0xffffffffu, s, o);
    if (lane == 0) {
        int b = row >> 11, n = row & 2047;
        float* dst = which ? g_kn : g_qn;
        dst[((b << 4) + h) * Nv + n] = s;
    }
}

// ---------------------------------------------------------------------------
// Fused hyperbolic flash attention (R1-proven, FFMA)
// ---------------------------------------------------------------------------
__device__ __forceinline__ float f_lg2(float x) { float r; asm("lg2.approx.f32 %0, %1;" : "=f"(r) : "f"(x)); return r; }
__device__ __forceinline__ float f_ex2(float x) { float r; asm("ex2.approx.f32 %0, %1;" : "=f"(r) : "f"(x)); return r; }
__device__ __forceinline__ float f_sqrt(float x){ float r; asm("sqrt.approx.f32 %0, %1;" : "=f"(r) : "f"(x)); return r; }

#define SW(d, c) (((d) << 6) + ((((((c) >> 2) ^ (((d) >> 2) & 15)) << 2)) | ((c) & 3)))

__global__ __launch_bounds__(256, 2)
void attn_kernel(const float* __restrict__ lc_p, const float* __restrict__ lb_p) {
    extern __shared__ float smem[];
    float* Qs = smem;
    float* Ks = smem + 4096;
    float* Vs = smem + 8192;
    float* Ps = smem + 12288;

    const int bh = blockIdx.y;
    const int b  = bh >> 4, h = bh & 15;
    const int qt = (int)gridDim.x - 1 - (int)blockIdx.x;
    const int t  = threadIdx.x;
    const int tx = t & 15, ty = t >> 4;

    const float cc = log1pf(expf(*lc_p));
    const float bb = log1pf(expf(*lb_p)) + 0.5f;
    const float L2E = 1.4426950408889634f;

    const float* Qbase = g_Q + ((size_t)(b * Nv + qt * 64)) * Dv + h * Dhv;
#pragma unroll
    for (int u = 0; u < 4; u++) {
        int id  = t + u * 256;
        int row = id >> 4;
        int d0  = (id & 15) << 2;
        float4 qv = *(const float4*)(Qbase + (size_t)row * Dv + d0);
        Qs[SW(d0 + 0, row)] = qv.x; Qs[SW(d0 + 1, row)] = qv.y;
        Qs[SW(d0 + 2, row)] = qv.z; Qs[SW(d0 + 3, row)] = qv.w;
    }

    float qnr[4];
    const float* qnp = g_qn + (size_t)bh * Nv + qt * 64;
#pragma unroll
    for (int i = 0; i < 4; i++) qnr[i] = qnp[ty * 4 + i];

    float m_i[4], l_i[4], acc[4][4];
#pragma unroll
    for (int i = 0; i < 4; i++) {
        m_i[i] = -1e30f; l_i[i] = 0.0f;
#pragma unroll
        for (int j = 0; j < 4; j++) acc[i][j] = 0.0f;
    }

    const float* Kbase0 = g_K + ((size_t)b * Nv) * Dv + h * Dhv;
    const float* Vbase0 = g_V + ((size_t)b * Nv) * Dv + h * Dhv;
    const float* knp    = g_kn + (size_t)bh * Nv;

    for (int kt = 0; kt <= qt; kt++) {
        __syncthreads();
        const float* Kb = Kbase0 + (size_t)kt * 64 * Dv;
        const float* Vb = Vbase0 + (size_t)kt * 64 * Dv;
#pragma unroll
        for (int u = 0; u < 4; u++) {
            int id  = t + u * 256;
            int row = id >> 4;
            int d0  = (id & 15) << 2;
            float4 kv = *(const float4*)(Kb + (size_t)row * Dv + d0);
            Ks[SW(d0 + 0, row)] = kv.x; Ks[SW(d0 + 1, row)] = kv.y;
            Ks[SW(d0 + 2, row)] = kv.z; Ks[SW(d0 + 3, row)] = kv.w;
            float4 vv = *(const float4*)(Vb + (size_t)row * Dv + d0);
            *(float4*)&Vs[(row << 6) + d0] = vv;
        }
        __syncthreads();

        float4 kn4 = *(const float4*)(knp + kt * 64 + tx * 4);
        const float knv[4] = { kn4.x, kn4.y, kn4.z, kn4.w };

        float s[4][4];
#pragma unroll
        for (int i = 0; i < 4; i++)
#pragma unroll
            for (int j = 0; j < 4; j++) s[i][j] = 0.0f;
#pragma unroll 8
        for (int d = 0; d < 64; d++) {
            float4 qv = *(const float4*)&Qs[(d << 6) + ((ty ^ ((d >> 2) & 15)) << 2)];
            float4 kv = *(const float4*)&Ks[(d << 6) + ((tx ^ ((d >> 2) & 15)) << 2)];
            s[0][0] = fmaf(qv.x, kv.x, s[0][0]); s[0][1] = fmaf(qv.x, kv.y, s[0][1]);
            s[0][2] = fmaf(qv.x, kv.z, s[0][2]); s[0][3] = fmaf(qv.x, kv.w, s[0][3]);
            s[1][0] = fmaf(qv.y, kv.x, s[1][0]); s[1][1] = fmaf(qv.y, kv.y, s[1][1]);
            s[1][2] = fmaf(qv.y, kv.z, s[1][2]); s[1][3] = fmaf(qv.y, kv.w, s[1][3]);
            s[2][0] = fmaf(qv.z, kv.x, s[2][0]); s[2][1] = fmaf(qv.z, kv.y, s[2][1]);
            s[2][2] = fmaf(qv.z, kv.z, s[2][2]); s[2][3] = fmaf(qv.z, kv.w, s[2][3]);
            s[3][0] = fmaf(qv.w, kv.x, s[3][0]); s[3][1] = fmaf(qv.w, kv.y, s[3][1]);
            s[3][2] = fmaf(qv.w, kv.z, s[3][2]); s[3][3] = fmaf(qv.w, kv.w, s[3][3]);
        }

#pragma unroll
        for (int i = 0; i < 4; i++)
#pragma unroll
            for (int j = 0; j < 4; j++) {
                float da = fmaxf(qnr[i] - 2.0f * s[i][j] + knv[j], 0.0f) + 1e-8f;
                float ns = qnr[i] + knv[j];
                float dist;
                if (da > 4.0f) {
                    dist = 0.693f + 0.34657359f * f_lg2(da) + cc * ns * 0.25f;
                } else {
                    float ed = f_sqrt(da);
                    if (ed < 0.1f) {
                        float cn = cc * ns;
                        dist = ed * (1.0f + 0.5f * cn + 0.125f * cn * cn);
                    } else if (ed > 2.0f) {
                        dist = 0.693f + 0.6931472f * f_lg2(ed + 1e-8f) + cc * ns * 0.25f;
                    } else {
                        dist = ed * f_sqrt(1.0f + cc * ns);
                    }
                }
                s[i][j] = -bb * dist;
            }

        if (kt == qt) {
#pragma unroll
            for (int i = 0; i < 4; i++)
#pragma unroll
                for (int j = 0; j < 4; j++)
                    if (4 * tx + j > 4 * ty + i) s[i][j] = -1e30f;
        }

#pragma unroll
        for (int i = 0; i < 4; i++) {
            float tm = fmaxf(fmaxf(s[i][0], s[i][1]), fmaxf(s[i][2], s[i][3]));
            tm = fmaxf(tm, __shfl_xor_sync(0xffffffffu, tm, 1));
            tm = fmaxf(tm, __shfl_xor_sync(0xffffffffu, tm, 2));
            tm = fmaxf(tm, __shfl_xor_sync(0xffffffffu, tm, 4));
            tm = fmaxf(tm, __shfl_xor_sync(0xffffffffu, tm, 8));
            float mn   = fmaxf(m_i[i], tm);
            float corr = f_ex2((m_i[i] - mn) * L2E);
            m_i[i] = mn;
            float rs = 0.0f;
#pragma unroll
            for (int j = 0; j < 4; j++) {
                float p = f_ex2((s[i][j] - mn) * L2E);
                s[i][j] = p; rs += p;
            }
            rs += __shfl_xor_sync(0xffffffffu, rs, 1);
            rs += __shfl_xor_sync(0xffffffffu, rs, 2);
            rs += __shfl_xor_sync(0xffffffffu, rs, 4);
            rs += __shfl_xor_sync(0xffffffffu, rs, 8);
            l_i[i] = l_i[i] * corr + rs;
#pragma unroll
            for (int j = 0; j < 4; j++) acc[i][j] *= corr;
        }

#pragma unroll
        for (int j = 0; j < 4; j++) {
            int c = 4 * tx + j;
            *(float4*)&Ps[(c << 6) + ((ty ^ tx) << 2)] =
                make_float4(s[0][j], s[1][j], s[2][j], s[3][j]);
        }
        __syncthreads();

#pragma unroll 8
        for (int kk = 0; kk < 64; kk++) {
            float4 pv = *(const float4*)&Ps[(kk << 6) + ((ty ^ (kk >> 2)) << 2)];
            float4 vv = *(const float4*)&Vs[(kk << 6) + (tx << 2)];
            acc[0][0] = fmaf(pv.x, vv.x, acc[0][0]); acc[0][1] = fmaf(pv.x, vv.y, acc[0][1]);
            acc[0][2] = fmaf(pv.x, vv.z, acc[0][2]); acc[0][3] = fmaf(pv.x, vv.w, acc[0][3]);
            acc[1][0] = fmaf(pv.y, vv.x, acc[1][0]); acc[1][1] = fmaf(pv.y, vv.y, acc[1][1]);
            acc[1][2] = fmaf(pv.y, vv.z, acc[1][2]); acc[1][3] = fmaf(pv.y, vv.w, acc[1][3]);
            acc[2][0] = fmaf(pv.z, vv.x, acc[2][0]); acc[2][1] = fmaf(pv.z, vv.y, acc[2][1]);
            acc[2][2] = fmaf(pv.z, vv.z, acc[2][2]); acc[2][3] = fmaf(pv.z, vv.w, acc[2][3]);
            acc[3][0] = fmaf(pv.w, vv.x, acc[3][0]); acc[3][1] = fmaf(pv.w, vv.y, acc[3][1]);
            acc[3][2] = fmaf(pv.w, vv.z, acc[3][2]); acc[3][3] = fmaf(pv.w, vv.w, acc[3][3]);
        }
    }

    float* Ob = g_O + ((size_t)(b * Nv + qt * 64)) * Dv + h * Dhv;
#pragma unroll
    for (int i = 0; i < 4; i++) {
        float inv = 1.0f / l_i[i];
        *(float4*)(Ob + (size_t)(ty * 4 + i) * Dv + tx * 4) =
            make_float4(acc[i][0] * inv, acc[i][1] * inv,
                        acc[i][2] * inv, acc[i][3] * inv);
    }
}

// ---------------------------------------------------------------------------
// Launch
// ---------------------------------------------------------------------------
extern "C" void kernel_launch(void* const* d_in, const int* in_sizes, int n_in,
                              void* d_out, int out_size) {
    const float* x  = (const float*)d_in[0];
    const float* Wq = (const float*)d_in[1];
    const float* Wk = (const float*)d_in[2];
    const float* Wv = (const float*)d_in[3];
    const float* Wo = (const float*)d_in[4];
    const float* lc = (const float*)d_in[5];
    const float* lb = (const float*)d_in[6];
    float* out = (float*)d_out;

    cudaFuncSetAttribute(proj_qkv_mma, cudaFuncAttributeMaxDynamicSharedMemorySize, GSMEM_BYTES);
    cudaFuncSetAttribute(out_proj_mma, cudaFuncAttributeMaxDynamicSharedMemorySize, GSMEM_BYTES);

    // 1) QKV projections: 3xBF16 mma.sync
    proj_qkv_mma<<<dim3(8, 32, 3), 256, GSMEM_BYTES>>>(x, Wq, Wk, Wv);

    // 2) norms
    norms_kernel<<<(2 * Mrows * Hv) / 8, 256>>>();

    // 3) fused hyperbolic flash attention
    const int asmem = 4 * 4096 * (int)sizeof(float);
    cudaFuncSetAttribute(attn_kernel, cudaFuncAttributeMaxDynamicSharedMemorySize, asmem);
    attn_kernel<<<dim3(Nv / 64, Bv * Hv), 256, asmem>>>(lc, lb);

    // 4) output projection into d_out
    out_proj_mma<<<dim3(8, 32), 256, GSMEM_BYTES>>>(Wo, out);
}

// round 4
// speedup vs baseline: 2.6245x; 1.7112x over previous
#include <cuda_runtime.h>
#include <cuda_fp16.h>
#include <math.h>
#include <stdint.h>

// Problem constants
#define Bv 2
#define Nv 2048
#define Dv 1024
#define Hv 16
#define Dhv 64
#define Mrows (Bv * Nv)   // 4096

// ---------------------------------------------------------------------------
// Scratch
// ---------------------------------------------------------------------------
__device__ float g_Q[Mrows * Dv];
__device__ float g_K[Mrows * Dv];
__device__ float g_V[Mrows * Dv];
__device__ float g_O[Mrows * Dv];
__device__ float g_qn[Bv * Hv * Nv];
__device__ float g_kn[Bv * Hv * Nv];

// ---------------------------------------------------------------------------
// Helpers (plain-sm_100-safe PTX only)
// ---------------------------------------------------------------------------
__device__ __forceinline__ uint32_t smem_u32(const void* p) {
    uint32_t a;
    asm("{ .reg .u64 t; cvta.to.shared.u64 t, %1; cvt.u32.u64 %0, t; }" : "=r"(a) : "l"(p));
    return a;
}

#define LDSM4(r0, r1, r2, r3, addr) \
    asm volatile("ldmatrix.sync.aligned.m8n8.x4.shared.b16 {%0,%1,%2,%3}, [%4];" \
        : "=r"(r0), "=r"(r1), "=r"(r2), "=r"(r3) : "r"(addr))
#define LDSM4T(r0, r1, r2, r3, addr) \
    asm volatile("ldmatrix.sync.aligned.m8n8.x4.trans.shared.b16 {%0,%1,%2,%3}, [%4];" \
        : "=r"(r0), "=r"(r1), "=r"(r2), "=r"(r3) : "r"(addr))

__device__ __forceinline__ void mma_bf16(float* d, const uint32_t* a, uint32_t b0, uint32_t b1) {
    asm volatile("mma.sync.aligned.m16n8k16.row.col.f32.bf16.bf16.f32 "
        "{%0,%1,%2,%3}, {%4,%5,%6,%7}, {%8,%9}, {%0,%1,%2,%3};"
        : "+f"(d[0]), "+f"(d[1]), "+f"(d[2]), "+f"(d[3])
        : "r"(a[0]), "r"(a[1]), "r"(a[2]), "r"(a[3]), "r"(b0), "r"(b1));
}
__device__ __forceinline__ void mma_f16(float* d, const uint32_t* a, uint32_t b0, uint32_t b1) {
    asm volatile("mma.sync.aligned.m16n8k16.row.col.f32.f16.f16.f32 "
        "{%0,%1,%2,%3}, {%4,%5,%6,%7}, {%8,%9}, {%0,%1,%2,%3};"
        : "+f"(d[0]), "+f"(d[1]), "+f"(d[2]), "+f"(d[3])
        : "r"(a[0]), "r"(a[1]), "r"(a[2]), "r"(a[3]), "r"(b0), "r"(b1));
}

__device__ __forceinline__ uint32_t pack_h2(float lo, float hi) {
    __half2 h = __floats2half2_rn(lo, hi);
    return *(uint32_t*)&h;
}

__device__ __forceinline__ float f_lg2(float x) { float r; asm("lg2.approx.f32 %0, %1;" : "=f"(r) : "f"(x)); return r; }
__device__ __forceinline__ float f_ex2(float x) { float r; asm("ex2.approx.f32 %0, %1;" : "=f"(r) : "f"(x)); return r; }
__device__ __forceinline__ float f_sqrt(float x){ float r; asm("sqrt.approx.f32 %0, %1;" : "=f"(r) : "f"(x)); return r; }

// ---------------------------------------------------------------------------
// 3xBF16 mma.sync GEMM (R3-proven, unchanged)
// ---------------------------------------------------------------------------
__device__ __forceinline__ void split_sts8(float4 v, uint32_t hi_addr, uint32_t lo_addr) {
    uint32_t h01, h23, l01, l23;
    asm("cvt.rn.bf16x2.f32 %0, %1, %2;" : "=r"(h01) : "f"(v.y), "f"(v.x));
    asm("cvt.rn.bf16x2.f32 %0, %1, %2;" : "=r"(h23) : "f"(v.w), "f"(v.z));
    float xl = v.x - __uint_as_float(h01 << 16);
    float yl = v.y - __uint_as_float(h01 & 0xffff0000u);
    float zl = v.z - __uint_as_float(h23 << 16);
    float wl = v.w - __uint_as_float(h23 & 0xffff0000u);
    asm("cvt.rn.bf16x2.f32 %0, %1, %2;" : "=r"(l01) : "f"(yl), "f"(xl));
    asm("cvt.rn.bf16x2.f32 %0, %1, %2;" : "=r"(l23) : "f"(wl), "f"(zl));
    asm volatile("st.shared.v2.b32 [%0], {%1,%2};" :: "r"(hi_addr), "r"(h01), "r"(h23) : "memory");
    asm volatile("st.shared.v2.b32 [%0], {%1,%2};" :: "r"(lo_addr), "r"(l01), "r"(l23) : "memory");
}

#define GSMEM_BYTES (65536 + 128)

__device__ void gemm3_body(const float* __restrict__ A, const float* __restrict__ W,
                           float* __restrict__ C) {
    extern __shared__ char sm_raw[];
    char* sm = (char*)(((uintptr_t)sm_raw + 127) & ~(uintptr_t)127);
    const uint32_t SB = smem_u32(sm);
    const uint32_t AH = SB, ALo = SB + 16384, WH = SB + 32768, WLo = SB + 49152;

    const int t  = threadIdx.x;
    const int L  = t & 31;
    const int wid = t >> 5;
    const int wm = wid >> 2;
    const int wn = wid & 3;
    const int m0 = blockIdx.y * 128;
    const int n0 = blockIdx.x * 128;

    const int srow = t >> 4, sc = t & 15;
    const float* pA = A + (size_t)(m0 + srow) * 1024 + sc * 4;
    const float* pW = W + (size_t)(n0 + srow) * 1024 + sc * 4;
    const uint32_t sts0 = (uint32_t)(srow * 128 + (((sc >> 1) ^ (srow & 7)) << 4) + (sc & 1) * 8);

    const uint32_t aBase = AH + (uint32_t)((wm * 64 + (L & 15)) * 128);
    const uint32_t bBase = WH + (uint32_t)((wn * 32 + ((L >> 4) & 1) * 8 + (L & 7)) * 128);
    uint32_t aXor[4], bXor[4];
#pragma unroll
    for (int js = 0; js < 4; js++) {
        aXor[js] = (uint32_t)((((js * 2 + (L >> 4)) ^ (L & 7)) << 4));
        bXor[js] = (uint32_t)((((js * 2 + ((L >> 3) & 1)) ^ (L & 7)) << 4));
    }

    float acc[4][4][4];
#pragma unroll
    for (int i = 0; i < 4; i++)
#pragma unroll
        for (int j = 0; j < 4; j++)
#pragma unroll
            for (int r = 0; r < 4; r++) acc[i][j][r] = 0.0f;

#pragma unroll 1
    for (int k = 0; k < 16; k++) {
        const int kb = k * 64;
        float4 av[4], wv[4];
#pragma unroll
        for (int u = 0; u < 4; u++) {
            av[u] = *(const float4*)(pA + (size_t)u * 16384 + kb);
            wv[u] = *(const float4*)(pW + (size_t)u * 16384 + kb);
        }
        __syncthreads();
#pragma unroll
        for (int u = 0; u < 4; u++) {
            uint32_t off = sts0 + u * 2048;
            split_sts8(av[u], AH + off, ALo + off);
            split_sts8(wv[u], WH + off, WLo + off);
        }
#pragma unroll
        for (int u = 0; u < 4; u++) {
            av[u] = *(const float4*)(pA + (size_t)(u + 4) * 16384 + kb);
            wv[u] = *(const float4*)(pW + (size_t)(u + 4) * 16384 + kb);
        }
#pragma unroll
        for (int u = 0; u < 4; u++) {
            uint32_t off = sts0 + (u + 4) * 2048;
            split_sts8(av[u], AH + off, ALo + off);
            split_sts8(wv[u], WH + off, WLo + off);
        }
        __syncthreads();

#pragma unroll
        for (int js = 0; js < 4; js++) {
            uint32_t ah[4][4], al[4][4];
#pragma unroll
            for (int i = 0; i < 4; i++) {
                LDSM4(ah[i][0], ah[i][1], ah[i][2], ah[i][3], aBase + i * 2048 + aXor[js]);
                LDSM4(al[i][0], al[i][1], al[i][2], al[i][3], aBase + 16384 + i * 2048 + aXor[js]);
            }
#pragma unroll
            for (int jp = 0; jp < 2; jp++) {
                uint32_t bh[4], bl[4];
                LDSM4(bh[0], bh[1], bh[2], bh[3], bBase + jp * 2048 + bXor[js]);
                LDSM4(bl[0], bl[1], bl[2], bl[3], bBase + 16384 + jp * 2048 + bXor[js]);
#pragma unroll
                for (int i = 0; i < 4; i++) {
                    mma_bf16(acc[i][jp * 2],     ah[i], bh[0], bh[1]);
                    mma_bf16(acc[i][jp * 2],     ah[i], bl[0], bl[1]);
                    mma_bf16(acc[i][jp * 2],     al[i], bh[0], bh[1]);
                    mma_bf16(acc[i][jp * 2 + 1], ah[i], bh[2], bh[3]);
                    mma_bf16(acc[i][jp * 2 + 1], ah[i], bl[2], bl[3]);
                    mma_bf16(acc[i][jp * 2 + 1], al[i], bh[2], bh[3]);
                }
            }
        }
    }

    const int rb = m0 + wm * 64 + (L >> 2);
    const int cb = n0 + wn * 32 + (L & 3) * 2;
#pragma unroll
    for (int i = 0; i < 4; i++)
#pragma unroll
        for (int j = 0; j < 4; j++) {
            const int r = rb + i * 16, cx = cb + j * 8;
            *(float2*)(C + (size_t)r * 1024 + cx)       = make_float2(acc[i][j][0], acc[i][j][1]);
            *(float2*)(C + (size_t)(r + 8) * 1024 + cx) = make_float2(acc[i][j][2], acc[i][j][3]);
        }
}

__global__ __launch_bounds__(256, 2)
void proj_qkv_mma(const float* __restrict__ x, const float* __restrict__ Wq,
                  const float* __restrict__ Wk, const float* __restrict__ Wv) {
    const float* W; float* C;
    if (blockIdx.z == 0)      { W = Wq; C = g_Q; }
    else if (blockIdx.z == 1) { W = Wk; C = g_K; }
    else                      { W = Wv; C = g_V; }
    gemm3_body(x, W, C);
}

__global__ __launch_bounds__(256, 2)
void out_proj_mma(const float* __restrict__ Wo, float* __restrict__ out) {
    gemm3_body(g_O, Wo, out);
}

// ---------------------------------------------------------------------------
// Norms
// ---------------------------------------------------------------------------
__global__ void norms_kernel() {
    int gid  = blockIdx.x * (blockDim.x >> 5) + (threadIdx.x >> 5);
    int lane = threadIdx.x & 31;
    const int total = 2 * Mrows * Hv;
    if (gid >= total) return;
    int which = gid >> 16;
    int rem   = gid & 65535;
    int row   = rem >> 4;
    int h     = rem & 15;
    const float* src = which ? g_K : g_Q;
    const float* p = src + (size_t)row * Dv + h * Dhv;
    float s = 0.0f;
#pragma unroll
    for (int i = lane; i < Dhv; i += 32) { float v = p[i]; s = fmaf(v, v, s); }
#pragma unroll
    for (int o = 16; o; o >>= 1) s += __shfl_xor_sync(0xffffffffu, s, o);
    if (lane == 0) {
        int b = row >> 11, n = row & 2047;
        float* dst = which ? g_kn : g_qn;
        dst[((b << 4) + h) * Nv + n] = s;
    }
}

// ---------------------------------------------------------------------------
// Fused hyperbolic flash attention, mma.sync version.
// CTA: 128 q-rows x Dh=64, 8 warps (warp = 16 q-rows x full 64 kv-cols).
// S = QK^T single fp16 mma; PV = 3-product fp16 split.
// ---------------------------------------------------------------------------
__global__ __launch_bounds__(256, 2)
void attn_mma_kernel(const float* __restrict__ lc_p, const float* __restrict__ lb_p) {
    __shared__ __align__(16) char QsBuf[16384];   // 128x64 fp16, SW128
    __shared__ __align__(16) char KsBuf[8192];    // 64x64 fp16
    __shared__ __align__(16) char VhBuf[8192];    // 64x64 fp16 (hi)
    __shared__ __align__(16) char VlBuf[8192];    // 64x64 fp16 (lo)
    __shared__ __align__(16) float Kn[64];

    const uint32_t Qs = smem_u32(QsBuf), Ks = smem_u32(KsBuf);
    const uint32_t Vh = smem_u32(VhBuf), Vl = smem_u32(VlBuf);

    const int t = threadIdx.x;
    const int L = t & 31;
    const int w = t >> 5;
    const int bh = blockIdx.y;
    const int b  = bh >> 4, h = bh & 15;
    const int qx = (int)gridDim.x - 1 - (int)blockIdx.x;   // big CTAs first
    const int qrow0 = qx * 128;
    const int wr0 = qrow0 + w * 16;                        // warp's first q row

    const float cc = log1pf(expf(*lc_p));
    const float bb = log1pf(expf(*lb_p)) + 0.5f;
    const float bL2E = bb * 1.4426950408889634f;
    const float C0 = -bL2E * 0.693f;
    const float C1 = -bL2E * 0.34657359f;       // -bL2E * 0.5*ln2... (0.6931472*0.5)
    const float C2 = -bL2E * cc * 0.25f;

    // ---- stage Q (fp32 -> fp16, SW128) ----
    {
        const float* Qg = g_Q + ((size_t)(b * Nv + qrow0)) * Dv + h * Dhv;
#pragma unroll
        for (int u = 0; u < 8; u++) {
            int idx = t + 256 * u;
            int row = idx >> 4, c4 = idx & 15;
            float4 v = *(const float4*)(Qg + (size_t)row * Dv + c4 * 4);
            uint32_t h01 = pack_h2(v.x, v.y), h23 = pack_h2(v.z, v.w);
            uint32_t addr = Qs + row * 128 + ((((c4 >> 1) ^ (row & 7)) << 4)) + (c4 & 1) * 8;
            asm volatile("st.shared.v2.b32 [%0], {%1,%2};" :: "r"(addr), "r"(h01), "r"(h23) : "memory");
        }
    }

    // per-lane q norms (rows r and r+8 of warp tile)
    const float qn0 = g_qn[(size_t)bh * Nv + wr0 + (L >> 2)];
    const float qn1 = g_qn[(size_t)bh * Nv + wr0 + (L >> 2) + 8];

    float o[8][4];
#pragma unroll
    for (int j = 0; j < 8; j++)
#pragma unroll
        for (int e = 0; e < 4; e++) o[j][e] = 0.0f;
    float m0r = -1e30f, m1r = -1e30f, l0r = 0.0f, l1r = 0.0f;

    const float* Kg0 = g_K + ((size_t)b * Nv) * Dv + h * Dhv;
    const float* Vg0 = g_V + ((size_t)b * Nv) * Dv + h * Dhv;
    const float* knp = g_kn + (size_t)bh * Nv;

    const int n_kt = 2 * qx + 2;
#pragma unroll 1
    for (int kt = 0; kt < n_kt; kt++) {
        const int k0 = kt * 64;
        __syncthreads();
        // ---- stage K (fp16) + V (fp16 hi/lo) + kn ----
        {
            const float* Kg = Kg0 + (size_t)k0 * Dv;
            const float* Vg = Vg0 + (size_t)k0 * Dv;
#pragma unroll
            for (int u = 0; u < 4; u++) {
                int idx = t + 256 * u;
                int row = idx >> 4, c4 = idx & 15;
                uint32_t off = (uint32_t)(row * 128 + ((((c4 >> 1) ^ (row & 7)) << 4)) + (c4 & 1) * 8);
                float4 kv = *(const float4*)(Kg + (size_t)row * Dv + c4 * 4);
                uint32_t k01 = pack_h2(kv.x, kv.y), k23 = pack_h2(kv.z, kv.w);
                asm volatile("st.shared.v2.b32 [%0], {%1,%2};" :: "r"(Ks + off), "r"(k01), "r"(k23) : "memory");
                float4 vv = *(const float4*)(Vg + (size_t)row * Dv + c4 * 4);
                uint32_t vh01 = pack_h2(vv.x, vv.y), vh23 = pack_h2(vv.z, vv.w);
                __half2 hh01 = *(__half2*)&vh01, hh23 = *(__half2*)&vh23;
                float2 b01 = __half22float2(hh01), b23 = __half22float2(hh23);
                uint32_t vl01 = pack_h2(vv.x - b01.x, vv.y - b01.y);
                uint32_t vl23 = pack_h2(vv.z - b23.x, vv.w - b23.y);
                asm volatile("st.shared.v2.b32 [%0], {%1,%2};" :: "r"(Vh + off), "r"(vh01), "r"(vh23) : "memory");
                asm volatile("st.shared.v2.b32 [%0], {%1,%2};" :: "r"(Vl + off), "r"(vl01), "r"(vl23) : "memory");
            }
            if (t < 16) *(float4*)&Kn[t * 4] = *(const float4*)(knp + k0 + t * 4);
        }
        __syncthreads();

        if (k0 > wr0 + 15) continue;   // all rows of this warp are above k-tile

        // ---- S = Q K^T (fp16 mma) ----
        float sc[8][4];
#pragma unroll
        for (int j = 0; j < 8; j++)
#pragma unroll
            for (int e = 0; e < 4; e++) sc[j][e] = 0.0f;

#pragma unroll
        for (int ks = 0; ks < 4; ks++) {
            uint32_t aq[4];
            {
                int arow = w * 16 + (L & 15);
                int ch = 2 * ks + (L >> 4);
                LDSM4(aq[0], aq[1], aq[2], aq[3], Qs + arow * 128 + (((ch ^ (arow & 7)) << 4)));
            }
#pragma unroll
            for (int jn = 0; jn < 4; jn++) {
                uint32_t bk[4];
                int brow = jn * 16 + ((L >> 4) & 1) * 8 + (L & 7);
                int ch = 2 * ks + ((L >> 3) & 1);
                LDSM4(bk[0], bk[1], bk[2], bk[3], Ks + brow * 128 + (((ch ^ (brow & 7)) << 4)));
                mma_f16(sc[2 * jn],     aq, bk[0], bk[1]);
                mma_f16(sc[2 * jn + 1], aq, bk[2], bk[3]);
            }
        }

        // ---- distance -> scores (log2 domain), mask ----
        const bool need_mask = (k0 + 63 > wr0);
        const int rg0 = wr0 + (L >> 2), rg1 = rg0 + 8;
        float vm0 = -1e30f, vm1 = -1e30f;
#pragma unroll
        for (int j = 0; j < 8; j++) {
            float2 kn2 = *(const float2*)&Kn[8 * j + 2 * (L & 3)];
            const int cg = k0 + 8 * j + 2 * (L & 3);
#pragma unroll
            for (int e = 0; e < 4; e++) {
                float qn = (e < 2) ? qn0 : qn1;
                float kn = (e & 1) ? kn2.y : kn2.x;
                float ns = qn + kn;
                float da = fmaxf(fmaf(-2.0f, sc[j][e], ns), 0.0f) + 1e-8f;
                float s2;
                if (da > 4.0f) {
                    s2 = fmaf(C1, f_lg2(da), fmaf(C2, ns, C0));
                } else {
                    float ed = f_sqrt(da);
                    float dist;
                    if (ed < 0.1f) {
                        float cn = cc * ns;
                        dist = ed * (1.0f + 0.5f * cn + 0.125f * cn * cn);
                    } else if (ed > 2.0f) {
                        dist = 0.693f + 0.6931472f * f_lg2(ed + 1e-8f) + cc * ns * 0.25f;
                    } else {
                        dist = ed * f_sqrt(1.0f + cc * ns);
                    }
                    s2 = -bL2E * dist;
                }
                if (need_mask) {
                    int rowg = (e < 2) ? rg0 : rg1;
                    if (cg + (e & 1) > rowg) s2 = -1e30f;
                }
                sc[j][e] = s2;
                if (e < 2) vm0 = fmaxf(vm0, s2); else vm1 = fmaxf(vm1, s2);
            }
        }
        // row reductions across the quad
        vm0 = fmaxf(vm0, __shfl_xor_sync(0xffffffffu, vm0, 1));
        vm0 = fmaxf(vm0, __shfl_xor_sync(0xffffffffu, vm0, 2));
        vm1 = fmaxf(vm1, __shfl_xor_sync(0xffffffffu, vm1, 1));
        vm1 = fmaxf(vm1, __shfl_xor_sync(0xffffffffu, vm1, 2));

        float mn0 = fmaxf(m0r, vm0), mn1 = fmaxf(m1r, vm1);
        float corr0 = f_ex2(m0r - mn0), corr1 = f_ex2(m1r - mn1);
        m0r = mn0; m1r = mn1;

        float rs0 = 0.0f, rs1 = 0.0f;
#pragma unroll
        for (int j = 0; j < 8; j++) {
            float p0 = f_ex2(sc[j][0] - mn0);
            float p1 = f_ex2(sc[j][1] - mn0);
            float p2 = f_ex2(sc[j][2] - mn1);
            float p3 = f_ex2(sc[j][3] - mn1);
            sc[j][0] = p0; sc[j][1] = p1; sc[j][2] = p2; sc[j][3] = p3;
            rs0 += p0 + p1; rs1 += p2 + p3;
        }
        rs0 += __shfl_xor_sync(0xffffffffu, rs0, 1);
        rs0 += __shfl_xor_sync(0xffffffffu, rs0, 2);
        rs1 += __shfl_xor_sync(0xffffffffu, rs1, 1);
        rs1 += __shfl_xor_sync(0xffffffffu, rs1, 2);
        l0r = l0r * corr0 + rs0;
        l1r = l1r * corr1 + rs1;
#pragma unroll
        for (int j = 0; j < 8; j++) {
            o[j][0] *= corr0; o[j][1] *= corr0;
            o[j][2] *= corr1; o[j][3] *= corr1;
        }

        // ---- PV: o += Ph*Vh + Pl*Vh + Ph*Vl (fp16 split) ----
#pragma unroll
        for (int ks = 0; ks < 4; ks++) {
            const int j0 = 2 * ks, j1 = 2 * ks + 1;
            uint32_t aph[4], apl[4];
            {
                uint32_t h0 = pack_h2(sc[j0][0], sc[j0][1]);
                uint32_t h1 = pack_h2(sc[j0][2], sc[j0][3]);
                uint32_t h2 = pack_h2(sc[j1][0], sc[j1][1]);
                uint32_t h3 = pack_h2(sc[j1][2], sc[j1][3]);
                aph[0] = h0; aph[1] = h1; aph[2] = h2; aph[3] = h3;
                float2 b0 = __half22float2(*(__half2*)&h0);
                float2 b1 = __half22float2(*(__half2*)&h1);
                float2 b2 = __half22float2(*(__half2*)&h2);
                float2 b3 = __half22float2(*(__half2*)&h3);
                apl[0] = pack_h2(sc[j0][0] - b0.x, sc[j0][1] - b0.y);
                apl[1] = pack_h2(sc[j0][2] - b1.x, sc[j0][3] - b1.y);
                apl[2] = pack_h2(sc[j1][0] - b2.x, sc[j1][1] - b2.y);
                apl[3] = pack_h2(sc[j1][2] - b3.x, sc[j1][3] - b3.y);
            }
            const int krow = 16 * ks + (L & 15);
#pragma unroll
            for (int jd = 0; jd < 4; jd++) {
                int ch = 2 * jd + (L >> 4);
                uint32_t voff = (uint32_t)(krow * 128 + (((ch ^ (krow & 7)) << 4)));
                uint32_t vhf[4], vlf[4];
                LDSM4T(vhf[0], vhf[1], vhf[2], vhf[3], Vh + voff);
                LDSM4T(vlf[0], vlf[1], vlf[2], vlf[3], Vl + voff);
                mma_f16(o[2 * jd],     aph, vhf[0], vhf[1]);
                mma_f16(o[2 * jd],     apl, vhf[0], vhf[1]);
                mma_f16(o[2 * jd],     aph, vlf[0], vlf[1]);
                mma_f16(o[2 * jd + 1], aph, vhf[2], vhf[3]);
                mma_f16(o[2 * jd + 1], apl, vhf[2], vhf[3]);
                mma_f16(o[2 * jd + 1], aph, vlf[2], vlf[3]);
            }
        }
    }

    // ---- epilogue ----
    const float inv0 = 1.0f / l0r, inv1 = 1.0f / l1r;
    float* Ob = g_O + ((size_t)(b * Nv + wr0 + (L >> 2))) * Dv + h * Dhv + 2 * (L & 3);
#pragma unroll
    for (int j = 0; j < 8; j++) {
        *(float2*)(Ob + 8 * j)              = make_float2(o[j][0] * inv0, o[j][1] * inv0);
        *(float2*)(Ob + 8 * (size_t)Dv + 8 * j) = make_float2(o[j][2] * inv1, o[j][3] * inv1);
    }
}

// ---------------------------------------------------------------------------
// Launch
// ---------------------------------------------------------------------------
extern "C" void kernel_launch(void* const* d_in, const int* in_sizes, int n_in,
                              void* d_out, int out_size) {
    const float* x  = (const float*)d_in[0];
    const float* Wq = (const float*)d_in[1];
    const float* Wk = (const float*)d_in[2];
    const float* Wv = (const float*)d_in[3];
    const float* Wo = (const float*)d_in[4];
    const float* lc = (const float*)d_in[5];
    const float* lb = (const float*)d_in[6];
    float* out = (float*)d_out;

    cudaFuncSetAttribute(proj_qkv_mma, cudaFuncAttributeMaxDynamicSharedMemorySize, GSMEM_BYTES);
    cudaFuncSetAttribute(out_proj_mma, cudaFuncAttributeMaxDynamicSharedMemorySize, GSMEM_BYTES);

    proj_qkv_mma<<<dim3(8, 32, 3), 256, GSMEM_BYTES>>>(x, Wq, Wk, Wv);
    norms_kernel<<<(2 * Mrows * Hv) / 8, 256>>>();
    attn_mma_kernel<<<dim3(Nv / 128, Bv * Hv), 256>>>(lc, lb);
    out_proj_mma<<<dim3(8, 32), 256, GSMEM_BYTES>>>(Wo, out);
}

// round 5
// speedup vs baseline: 2.7976x; 1.0660x over previous
#include <cuda_runtime.h>
#include <cuda_fp16.h>
#include <cuda_bf16.h>
#include <math.h>
#include <stdint.h>

#define Bv 2
#define Nv 2048
#define Dv 1024
#define Hv 16
#define Dhv 64
#define Mrows (Bv * Nv)   // 4096

// ---------------------------------------------------------------------------
// Scratch (all pre-split / packed formats)
// ---------------------------------------------------------------------------
__device__ __nv_bfloat16 g_xh[Mrows * Dv], g_xl[Mrows * Dv];
__device__ __nv_bfloat16 g_Wqh[Dv * Dv], g_Wql[Dv * Dv];
__device__ __nv_bfloat16 g_Wkh[Dv * Dv], g_Wkl[Dv * Dv];
__device__ __nv_bfloat16 g_Wvh[Dv * Dv], g_Wvl[Dv * Dv];
__device__ __nv_bfloat16 g_Woh[Dv * Dv], g_Wol[Dv * Dv];
__device__ __half        g_Qh[Mrows * Dv], g_Kh[Mrows * Dv];
__device__ __half        g_Vh[Mrows * Dv], g_Vl[Mrows * Dv];
__device__ __nv_bfloat16 g_Oh[Mrows * Dv], g_Ol[Mrows * Dv];
__device__ float         g_qn[Bv * Hv * Nv], g_kn[Bv * Hv * Nv];

// ---------------------------------------------------------------------------
// Helpers (plain-sm_100-safe PTX only)
// ---------------------------------------------------------------------------
__device__ __forceinline__ uint32_t smem_u32(const void* p) {
    uint32_t a;
    asm("{ .reg .u64 t; cvta.to.shared.u64 t, %1; cvt.u32.u64 %0, t; }" : "=r"(a) : "l"(p));
    return a;
}
__device__ __forceinline__ void cp16(uint32_t dst, const void* src) {
    asm volatile("cp.async.cg.shared.global [%0], [%1], 16;" :: "r"(dst), "l"(src) : "memory");
}
#define CP_COMMIT() asm volatile("cp.async.commit_group;" ::: "memory")
#define CP_WAIT(n)  asm volatile("cp.async.wait_group %0;" :: "n"(n) : "memory")

#define LDSM4(r0, r1, r2, r3, addr) \
    asm volatile("ldmatrix.sync.aligned.m8n8.x4.shared.b16 {%0,%1,%2,%3}, [%4];" \
        : "=r"(r0), "=r"(r1), "=r"(r2), "=r"(r3) : "r"(addr))
#define LDSM4T(r0, r1, r2, r3, addr) \
    asm volatile("ldmatrix.sync.aligned.m8n8.x4.trans.shared.b16 {%0,%1,%2,%3}, [%4];" \
        : "=r"(r0), "=r"(r1), "=r"(r2), "=r"(r3) : "r"(addr))

__device__ __forceinline__ void mma_bf16(float* d, const uint32_t* a, uint32_t b0, uint32_t b1) {
    asm volatile("mma.sync.aligned.m16n8k16.row.col.f32.bf16.bf16.f32 "
        "{%0,%1,%2,%3}, {%4,%5,%6,%7}, {%8,%9}, {%0,%1,%2,%3};"
        : "+f"(d[0]), "+f"(d[1]), "+f"(d[2]), "+f"(d[3])
        : "r"(a[0]), "r"(a[1]), "r"(a[2]), "r"(a[3]), "r"(b0), "r"(b1));
}
__device__ __forceinline__ void mma_f16(float* d, const uint32_t* a, uint32_t b0, uint32_t b1) {
    asm volatile("mma.sync.aligned.m16n8k16.row.col.f32.f16.f16.f32 "
        "{%0,%1,%2,%3}, {%4,%5,%6,%7}, {%8,%9}, {%0,%1,%2,%3};"
        : "+f"(d[0]), "+f"(d[1]), "+f"(d[2]), "+f"(d[3])
        : "r"(a[0]), "r"(a[1]), "r"(a[2]), "r"(a[3]), "r"(b0), "r"(b1));
}

__device__ __forceinline__ uint32_t pack_h2(float lo, float hi) {
    __half2 h = __floats2half2_rn(lo, hi);
    return *(uint32_t*)&h;
}
// (a,b) -> bf16x2 hi pair + bf16x2 lo pair
__device__ __forceinline__ void bfsplit2(float a, float b, uint32_t& h, uint32_t& l) {
    asm("cvt.rn.bf16x2.f32 %0, %1, %2;" : "=r"(h) : "f"(b), "f"(a));
    float al = a - __uint_as_float(h << 16);
    float bl = b - __uint_as_float(h & 0xffff0000u);
    asm("cvt.rn.bf16x2.f32 %0, %1, %2;" : "=r"(l) : "f"(bl), "f"(al));
}

__device__ __forceinline__ float f_lg2(float x) { float r; asm("lg2.approx.f32 %0, %1;" : "=f"(r) : "f"(x)); return r; }
__device__ __forceinline__ float f_ex2(float x) { float r; asm("ex2.approx.f32 %0, %1;" : "=f"(r) : "f"(x)); return r; }
__device__ __forceinline__ float f_sqrt(float x){ float r; asm("sqrt.approx.f32 %0, %1;" : "=f"(r) : "f"(x)); return r; }

// ---------------------------------------------------------------------------
// Prep: split fp32 sources into bf16 hi/lo arrays (one pass)
// ---------------------------------------------------------------------------
__global__ void prep_split(const float* __restrict__ x, const float* __restrict__ Wq,
                           const float* __restrict__ Wk, const float* __restrict__ Wv,
                           const float* __restrict__ Wo) {
    const float* src; __nv_bfloat16 *hi, *lo; int n;
    switch (blockIdx.z) {
        case 0:  src = x;  hi = g_xh;  lo = g_xl;  n = Mrows * Dv; break;
        case 1:  src = Wq; hi = g_Wqh; lo = g_Wql; n = Dv * Dv;    break;
        case 2:  src = Wk; hi = g_Wkh; lo = g_Wkl; n = Dv * Dv;    break;
        case 3:  src = Wv; hi = g_Wvh; lo = g_Wvl; n = Dv * Dv;    break;
        default: src = Wo; hi = g_Woh; lo = g_Wol; n = Dv * Dv;    break;
    }
    int i = (blockIdx.x * 256 + threadIdx.x) * 4;
    if (i >= n) return;
    float4 v = *(const float4*)(src + i);
    uint32_t h01, l01, h23, l23;
    bfsplit2(v.x, v.y, h01, l01);
    bfsplit2(v.z, v.w, h23, l23);
    *(uint32_t*)(hi + i) = h01; *(uint32_t*)(hi + i + 2) = h23;
    *(uint32_t*)(lo + i) = l01; *(uint32_t*)(lo + i + 2) = l23;
}

// ---------------------------------------------------------------------------
// 3xBF16 GEMM, cp.async double-buffered. C = A @ W^T, tile 128x128, K=1024.
// Stage = 4 bf16 tiles (Ah|Al|Wh|Wl) x 16KB = 64KB; 2 stages = 128KB smem.
// mode 0/1: write fp16 + norms; mode 2: fp16 hi/lo; mode 3: fp32.
// ---------------------------------------------------------------------------
#define GSTAGE    65536
#define GEMM_SMEM (2 * GSTAGE)

__device__ __forceinline__ void gemm_cp_body(
    const __nv_bfloat16* __restrict__ Ah, const __nv_bfloat16* __restrict__ Al,
    const __nv_bfloat16* __restrict__ Wh, const __nv_bfloat16* __restrict__ Wl,
    int mode, __half* outH, __half* outL, float* fout, float* nrm_out)
{
    extern __shared__ char smem[];
    const uint32_t SB = smem_u32(smem);
    const int t = threadIdx.x, L = t & 31, wid = t >> 5;
    const int wm = wid >> 2, wn = wid & 3;
    const int m0 = blockIdx.y * 128, n0 = blockIdx.x * 128;

    auto issue = [&](int k0, uint32_t sbase) {
#pragma unroll
        for (int u = 0; u < 16; u++) {
            int idx = t + 256 * u;
            int tile = idx >> 10, r = (idx >> 3) & 127, ch = idx & 7;
            const __nv_bfloat16* base = (tile == 0) ? Ah : (tile == 1) ? Al : (tile == 2) ? Wh : Wl;
            int grow = ((tile < 2) ? m0 : n0) + r;
            const void* src = base + (size_t)grow * 1024 + k0 + ch * 8;
            cp16(sbase + tile * 16384 + r * 128 + ((ch ^ (r & 7)) << 4), src);
        }
        CP_COMMIT();
    };

    issue(0, SB);
    issue(64, SB + GSTAGE);

    const uint32_t aOff = (uint32_t)((wm * 64 + (L & 15)) * 128);
    const uint32_t bOff = (uint32_t)(32768 + (wn * 32 + ((L >> 4) & 1) * 8 + (L & 7)) * 128);
    uint32_t aXor[4], bXor[4];
#pragma unroll
    for (int js = 0; js < 4; js++) {
        aXor[js] = (uint32_t)(((js * 2 + (L >> 4)) ^ (L & 7)) << 4);
        bXor[js] = (uint32_t)(((js * 2 + ((L >> 3) & 1)) ^ (L & 7)) << 4);
    }

    float acc[4][4][4];
#pragma unroll
    for (int i = 0; i < 4; i++)
#pragma unroll
        for (int j = 0; j < 4; j++)
#pragma unroll
            for (int r = 0; r < 4; r++) acc[i][j][r] = 0.0f;

#pragma unroll 1
    for (int k = 0; k < 16; k++) {
        if (k + 1 < 16) { CP_WAIT(1); } else { CP_WAIT(0); }
        __syncthreads();
        const uint32_t sb = SB + (uint32_t)(k & 1) * GSTAGE;
#pragma unroll
        for (int js = 0; js < 4; js++) {
            uint32_t ah[4][4], al[4][4];
#pragma unroll
            for (int i = 0; i < 4; i++) {
                LDSM4(ah[i][0], ah[i][1], ah[i][2], ah[i][3], sb + aOff + i * 2048 + aXor[js]);
                LDSM4(al[i][0], al[i][1], al[i][2], al[i][3], sb + 16384 + aOff + i * 2048 + aXor[js]);
            }
#pragma unroll
            for (int jp = 0; jp < 2; jp++) {
                uint32_t bh[4], bl[4];
                LDSM4(bh[0], bh[1], bh[2], bh[3], sb + bOff + jp * 2048 + bXor[js]);
                LDSM4(bl[0], bl[1], bl[2], bl[3], sb + 16384 + bOff + jp * 2048 + bXor[js]);
#pragma unroll
                for (int i = 0; i < 4; i++) {
                    mma_bf16(acc[i][jp * 2],     ah[i], bh[0], bh[1]);
                    mma_bf16(acc[i][jp * 2],     ah[i], bl[0], bl[1]);
                    mma_bf16(acc[i][jp * 2],     al[i], bh[0], bh[1]);
                    mma_bf16(acc[i][jp * 2 + 1], ah[i], bh[2], bh[3]);
                    mma_bf16(acc[i][jp * 2 + 1], ah[i], bl[2], bl[3]);
                    mma_bf16(acc[i][jp * 2 + 1], al[i], bh[2], bh[3]);
                }
            }
        }
        __syncthreads();
        if (k + 2 < 16) issue((k + 2) * 64, sb);
    }

    // ---- epilogues ----
    const int rb = m0 + wm * 64 + (L >> 2);
    const int cb = n0 + wn * 32 + (L & 3) * 2;

    if (mode <= 1) {                 // Q or K: fp16 out + exact fp32 norms
        float p0s[4], p1s[4];
#pragma unroll
        for (int i = 0; i < 4; i++) {
            float s0 = 0.0f, s1 = 0.0f;
#pragma unroll
            for (int j = 0; j < 4; j++) {
                const int r = rb + i * 16, c = cb + j * 8;
                *(__half2*)(outH + (size_t)r * 1024 + c)       = __floats2half2_rn(acc[i][j][0], acc[i][j][1]);
                *(__half2*)(outH + (size_t)(r + 8) * 1024 + c) = __floats2half2_rn(acc[i][j][2], acc[i][j][3]);
                s0 = fmaf(acc[i][j][0], acc[i][j][0], fmaf(acc[i][j][1], acc[i][j][1], s0));
                s1 = fmaf(acc[i][j][2], acc[i][j][2], fmaf(acc[i][j][3], acc[i][j][3], s1));
            }
            s0 += __shfl_xor_sync(0xffffffffu, s0, 1);
            s0 += __shfl_xor_sync(0xffffffffu, s0, 2);
            s1 += __shfl_xor_sync(0xffffffffu, s1, 1);
            s1 += __shfl_xor_sync(0xffffffffu, s1, 2);
            p0s[i] = s0; p1s[i] = s1;
        }
        __syncthreads();                       // stage smem now free
        float* part = (float*)smem;            // [128][4]
        if ((L & 3) == 0) {
#pragma unroll
            for (int i = 0; i < 4; i++) {
                int r0 = wm * 64 + (L >> 2) + i * 16;
                part[r0 * 4 + wn] = p0s[i];
                part[(r0 + 8) * 4 + wn] = p1s[i];
            }
        }
        __syncthreads();
        {
            int row = t >> 1, ph = t & 1;
            float s = part[row * 4 + 2 * ph] + part[row * 4 + 2 * ph + 1];
            int grow = m0 + row, head = (n0 >> 6) + ph;
            int b = grow >> 11, n = grow & 2047;
            nrm_out[((b << 4) + head) * Nv + n] = s;
        }
    } else if (mode == 2) {          // V: fp16 hi/lo
#pragma unroll
        for (int i = 0; i < 4; i++)
#pragma unroll
            for (int j = 0; j < 4; j++) {
                const int r = rb + i * 16, c = cb + j * 8;
                __half2 h0 = __floats2half2_rn(acc[i][j][0], acc[i][j][1]);
                __half2 h1 = __floats2half2_rn(acc[i][j][2], acc[i][j][3]);
                float2 f0 = __half22float2(h0), f1 = __half22float2(h1);
                __half2 l0 = __floats2half2_rn(acc[i][j][0] - f0.x, acc[i][j][1] - f0.y);
                __half2 l1 = __floats2half2_rn(acc[i][j][2] - f1.x, acc[i][j][3] - f1.y);
                *(__half2*)(outH + (size_t)r * 1024 + c)       = h0;
                *(__half2*)(outH + (size_t)(r + 8) * 1024 + c) = h1;
                *(__half2*)(outL + (size_t)r * 1024 + c)       = l0;
                *(__half2*)(outL + (size_t)(r + 8) * 1024 + c) = l1;
            }
    } else {                         // fp32 final output
#pragma unroll
        for (int i = 0; i < 4; i++)
#pragma unroll
            for (int j = 0; j < 4; j++) {
                const int r = rb + i * 16, cx = cb + j * 8;
                *(float2*)(fout + (size_t)r * 1024 + cx)       = make_float2(acc[i][j][0], acc[i][j][1]);
                *(float2*)(fout + (size_t)(r + 8) * 1024 + cx) = make_float2(acc[i][j][2], acc[i][j][3]);
            }
    }
}

__global__ __launch_bounds__(256, 1)
void proj_qkv_cp() {
    if (blockIdx.z == 0)
        gemm_cp_body(g_xh, g_xl, g_Wqh, g_Wql, 0, g_Qh, nullptr, nullptr, g_qn);
    else if (blockIdx.z == 1)
        gemm_cp_body(g_xh, g_xl, g_Wkh, g_Wkl, 1, g_Kh, nullptr, nullptr, g_kn);
    else
        gemm_cp_body(g_xh, g_xl, g_Wvh, g_Wvl, 2, g_Vh, g_Vl, nullptr, nullptr);
}

__global__ __launch_bounds__(256, 1)
void out_proj_cp(float* __restrict__ out) {
    gemm_cp_body(g_Oh, g_Ol, g_Woh, g_Wol, 3, nullptr, nullptr, out, nullptr);
}

// ---------------------------------------------------------------------------
// Hyperbolic flash attention, cp.async double-buffered, mma.sync.
// CTA: 128 q-rows, 8 warps (16 rows each). Stages: K | Vh | Vl (8KB each).
// ---------------------------------------------------------------------------
#define AST0  16384
#define ASTSZ 24576
#define AKN   (16384 + 2 * ASTSZ)          // 65536
#define ASMEM (AKN + 2 * 256)              // 66048

__global__ __launch_bounds__(256, 2)
void attn_cp(const float* __restrict__ lc_p, const float* __restrict__ lb_p) {
    extern __shared__ char smem[];
    const uint32_t SB = smem_u32(smem);
    const uint32_t QS = SB;

    const int t = threadIdx.x;
    const int L = t & 31;
    const int w = t >> 5;
    const int bh = blockIdx.y;
    const int b  = bh >> 4, h = bh & 15;
    const int qx = (int)gridDim.x - 1 - (int)blockIdx.x;
    const int qrow0 = qx * 128;
    const int wr0 = qrow0 + w * 16;

    const float cc = log1pf(expf(*lc_p));
    const float bb = log1pf(expf(*lb_p)) + 0.5f;
    const float bL2E = bb * 1.4426950408889634f;
    const float C0 = -bL2E * 0.693f;
    const float C1 = -bL2E * 0.34657359f;
    const float C2 = -bL2E * cc * 0.25f;

    const int n_kt = 2 * qx + 2;

    auto issueKV = [&](int kt) {
        const int k0 = kt * 64;
        const uint32_t sb = SB + AST0 + (uint32_t)(kt & 1) * ASTSZ;
#pragma unroll
        for (int u = 0; u < 6; u++) {
            int idx = t + 256 * u;
            int tile = idx >> 9, r = (idx >> 3) & 63, ch = idx & 7;
            const __half* base = (tile == 0) ? g_Kh : (tile == 1) ? g_Vh : g_Vl;
            const void* src = base + (size_t)(b * Nv + k0 + r) * Dv + h * Dhv + ch * 8;
            cp16(sb + tile * 8192 + r * 128 + ((ch ^ (r & 7)) << 4), src);
        }
        if (t < 16)
            cp16(SB + AKN + (kt & 1) * 256 + t * 16, g_kn + (size_t)bh * Nv + k0 + t * 4);
        CP_COMMIT();
    };

    // prologue: Q bundled into group 0
#pragma unroll
    for (int u = 0; u < 4; u++) {
        int idx = t + 256 * u;
        int r = idx >> 3, ch = idx & 7;
        const void* src = g_Qh + (size_t)(b * Nv + qrow0 + r) * Dv + h * Dhv + ch * 8;
        cp16(QS + r * 128 + ((ch ^ (r & 7)) << 4), src);
    }
    issueKV(0);
    if (n_kt > 1) issueKV(1);

    const float qn0 = g_qn[(size_t)bh * Nv + wr0 + (L >> 2)];
    const float qn1 = g_qn[(size_t)bh * Nv + wr0 + (L >> 2) + 8];

    float o[8][4];
#pragma unroll
    for (int j = 0; j < 8; j++)
#pragma unroll
        for (int e = 0; e < 4; e++) o[j][e] = 0.0f;
    float m0r = -1e30f, m1r = -1e30f, l0r = 0.0f, l1r = 0.0f;

#pragma unroll 1
    for (int kt = 0; kt < n_kt; kt++) {
        if (kt + 1 < n_kt) { CP_WAIT(1); } else { CP_WAIT(0); }
        __syncthreads();
        const int k0 = kt * 64;
        const uint32_t sb = SB + AST0 + (uint32_t)(kt & 1) * ASTSZ;
        const float* kn_s = (const float*)(smem + AKN + (kt & 1) * 256);

        if (k0 <= wr0 + 15) {
            // ---- S = Q K^T (fp16 mma) ----
            float sc[8][4];
#pragma unroll
            for (int j = 0; j < 8; j++)
#pragma unroll
                for (int e = 0; e < 4; e++) sc[j][e] = 0.0f;
#pragma unroll
            for (int ks = 0; ks < 4; ks++) {
                uint32_t aq[4];
                {
                    int arow = w * 16 + (L & 15);
                    int ch = 2 * ks + (L >> 4);
                    LDSM4(aq[0], aq[1], aq[2], aq[3], QS + arow * 128 + ((ch ^ (arow & 7)) << 4));
                }
#pragma unroll
                for (int jn = 0; jn < 4; jn++) {
                    uint32_t bk[4];
                    int brow = jn * 16 + ((L >> 4) & 1) * 8 + (L & 7);
                    int ch = 2 * ks + ((L >> 3) & 1);
                    LDSM4(bk[0], bk[1], bk[2], bk[3], sb + brow * 128 + ((ch ^ (brow & 7)) << 4));
                    mma_f16(sc[2 * jn],     aq, bk[0], bk[1]);
                    mma_f16(sc[2 * jn + 1], aq, bk[2], bk[3]);
                }
            }

            // ---- distance -> scores, mask ----
            const bool need_mask = (k0 + 63 > wr0);
            const int rg0 = wr0 + (L >> 2), rg1 = rg0 + 8;
            float vm0 = -1e30f, vm1 = -1e30f;
#pragma unroll
            for (int j = 0; j < 8; j++) {
                float2 kn2 = *(const float2*)(kn_s + 8 * j + 2 * (L & 3));
                const int cg = k0 + 8 * j + 2 * (L & 3);
#pragma unroll
                for (int e = 0; e < 4; e++) {
                    float qn = (e < 2) ? qn0 : qn1;
                    float kn = (e & 1) ? kn2.y : kn2.x;
                    float ns = qn + kn;
                    float da = fmaxf(fmaf(-2.0f, sc[j][e], ns), 0.0f) + 1e-8f;
                    float s2;
                    if (da > 4.0f) {
                        s2 = fmaf(C1, f_lg2(da), fmaf(C2, ns, C0));
                    } else {
                        float ed = f_sqrt(da);
                        float dist;
                        if (ed < 0.1f) {
                            float cn = cc * ns;
                            dist = ed * (1.0f + 0.5f * cn + 0.125f * cn * cn);
                        } else if (ed > 2.0f) {
                            dist = 0.693f + 0.6931472f * f_lg2(ed + 1e-8f) + cc * ns * 0.25f;
                        } else {
                            dist = ed * f_sqrt(1.0f + cc * ns);
                        }
                        s2 = -bL2E * dist;
                    }
                    if (need_mask) {
                        int rowg = (e < 2) ? rg0 : rg1;
                        if (cg + (e & 1) > rowg) s2 = -1e30f;
                    }
                    sc[j][e] = s2;
                    if (e < 2) vm0 = fmaxf(vm0, s2); else vm1 = fmaxf(vm1, s2);
                }
            }
            vm0 = fmaxf(vm0, __shfl_xor_sync(0xffffffffu, vm0, 1));
            vm0 = fmaxf(vm0, __shfl_xor_sync(0xffffffffu, vm0, 2));
            vm1 = fmaxf(vm1, __shfl_xor_sync(0xffffffffu, vm1, 1));
            vm1 = fmaxf(vm1, __shfl_xor_sync(0xffffffffu, vm1, 2));

            float mn0 = fmaxf(m0r, vm0), mn1 = fmaxf(m1r, vm1);
            float corr0 = f_ex2(m0r - mn0), corr1 = f_ex2(m1r - mn1);
            m0r = mn0; m1r = mn1;

            float rs0 = 0.0f, rs1 = 0.0f;
#pragma unroll
            for (int j = 0; j < 8; j++) {
                float p0 = f_ex2(sc[j][0] - mn0);
                float p1 = f_ex2(sc[j][1] - mn0);
                float p2 = f_ex2(sc[j][2] - mn1);
                float p3 = f_ex2(sc[j][3] - mn1);
                sc[j][0] = p0; sc[j][1] = p1; sc[j][2] = p2; sc[j][3] = p3;
                rs0 += p0 + p1; rs1 += p2 + p3;
            }
            rs0 += __shfl_xor_sync(0xffffffffu, rs0, 1);
            rs0 += __shfl_xor_sync(0xffffffffu, rs0, 2);
            rs1 += __shfl_xor_sync(0xffffffffu, rs1, 1);
            rs1 += __shfl_xor_sync(0xffffffffu, rs1, 2);
            l0r = l0r * corr0 + rs0;
            l1r = l1r * corr1 + rs1;
#pragma unroll
            for (int j = 0; j < 8; j++) {
                o[j][0] *= corr0; o[j][1] *= corr0;
                o[j][2] *= corr1; o[j][3] *= corr1;
            }

            // ---- PV: o += Ph*Vh + Pl*Vh + Ph*Vl ----
#pragma unroll
            for (int ks = 0; ks < 4; ks++) {
                const int j0 = 2 * ks, j1 = 2 * ks + 1;
                uint32_t aph[4], apl[4];
                {
                    uint32_t h0 = pack_h2(sc[j0][0], sc[j0][1]);
                    uint32_t h1 = pack_h2(sc[j0][2], sc[j0][3]);
                    uint32_t h2 = pack_h2(sc[j1][0], sc[j1][1]);
                    uint32_t h3 = pack_h2(sc[j1][2], sc[j1][3]);
                    aph[0] = h0; aph[1] = h1; aph[2] = h2; aph[3] = h3;
                    float2 b0 = __half22float2(*(__half2*)&h0);
                    float2 b1 = __half22float2(*(__half2*)&h1);
                    float2 b2 = __half22float2(*(__half2*)&h2);
                    float2 b3 = __half22float2(*(__half2*)&h3);
                    apl[0] = pack_h2(sc[j0][0] - b0.x, sc[j0][1] - b0.y);
                    apl[1] = pack_h2(sc[j0][2] - b1.x, sc[j0][3] - b1.y);
                    apl[2] = pack_h2(sc[j1][0] - b2.x, sc[j1][1] - b2.y);
                    apl[3] = pack_h2(sc[j1][2] - b3.x, sc[j1][3] - b3.y);
                }
                const int krow = 16 * ks + (L & 15);
#pragma unroll
                for (int jd = 0; jd < 4; jd++) {
                    int ch = 2 * jd + (L >> 4);
                    uint32_t voff = (uint32_t)(krow * 128 + ((ch ^ (krow & 7)) << 4));
                    uint32_t vhf[4], vlf[4];
                    LDSM4T(vhf[0], vhf[1], vhf[2], vhf[3], sb + 8192 + voff);
                    LDSM4T(vlf[0], vlf[1], vlf[2], vlf[3], sb + 16384 + voff);
                    mma_f16(o[2 * jd],     aph, vhf[0], vhf[1]);
                    mma_f16(o[2 * jd],     apl, vhf[0], vhf[1]);
                    mma_f16(o[2 * jd],     aph, vlf[0], vlf[1]);
                    mma_f16(o[2 * jd + 1], aph, vhf[2], vhf[3]);
                    mma_f16(o[2 * jd + 1], apl, vhf[2], vhf[3]);
                    mma_f16(o[2 * jd + 1], aph, vlf[2], vlf[3]);
                }
            }
        }
        __syncthreads();
        if (kt + 2 < n_kt) issueKV(kt + 2);
    }

    // ---- epilogue: O normalized, written pre-split as bf16 hi/lo ----
    const float inv0 = 1.0f / l0r, inv1 = 1.0f / l1r;
    const size_t base0 = (size_t)(b * Nv + wr0 + (L >> 2)) * Dv + h * Dhv + 2 * (L & 3);
    const size_t base1 = base0 + 8 * (size_t)Dv;
#pragma unroll
    for (int j = 0; j < 8; j++) {
        uint32_t hh, ll;
        bfsplit2(o[j][0] * inv0, o[j][1] * inv0, hh, ll);
        *(uint32_t*)(g_Oh + base0 + 8 * j) = hh;
        *(uint32_t*)(g_Ol + base0 + 8 * j) = ll;
        bfsplit2(o[j][2] * inv1, o[j][3] * inv1, hh, ll);
        *(uint32_t*)(g_Oh + base1 + 8 * j) = hh;
        *(uint32_t*)(g_Ol + base1 + 8 * j) = ll;
    }
}

// ---------------------------------------------------------------------------
// Launch
// ---------------------------------------------------------------------------
extern "C" void kernel_launch(void* const* d_in, const int* in_sizes, int n_in,
                              void* d_out, int out_size) {
    const float* x  = (const float*)d_in[0];
    const float* Wq = (const float*)d_in[1];
    const float* Wk = (const float*)d_in[2];
    const float* Wv = (const float*)d_in[3];
    const float* Wo = (const float*)d_in[4];
    const float* lc = (const float*)d_in[5];
    const float* lb = (const float*)d_in[6];
    float* out = (float*)d_out;

    cudaFuncSetAttribute(proj_qkv_cp, cudaFuncAttributeMaxDynamicSharedMemorySize, GEMM_SMEM);
    cudaFuncSetAttribute(out_proj_cp, cudaFuncAttributeMaxDynamicSharedMemorySize, GEMM_SMEM);
    cudaFuncSetAttribute(attn_cp,     cudaFuncAttributeMaxDynamicSharedMemorySize, ASMEM);

    prep_split<<<dim3(4096, 1, 5), 256>>>(x, Wq, Wk, Wv, Wo);
    proj_qkv_cp<<<dim3(8, 32, 3), 256, GEMM_SMEM>>>();
    attn_cp<<<dim3(Nv / 128, Bv * Hv), 256, ASMEM>>>(lc, lb);
    out_proj_cp<<<dim3(8, 32), 256, GEMM_SMEM>>>(out);
}

// round 6
// speedup vs baseline: 2.8135x; 1.0057x over previous
#include <cuda_runtime.h>
#include <cuda_fp16.h>
#include <cuda_bf16.h>
#include <math.h>
#include <stdint.h>

#define Bv 2
#define Nv 2048
#define Dv 1024
#define Hv 16
#define Dhv 64
#define Mrows (Bv * Nv)   // 4096

// ---------------------------------------------------------------------------
// Scratch (all pre-split / packed formats)
// ---------------------------------------------------------------------------
__device__ __nv_bfloat16 g_xh[Mrows * Dv], g_xl[Mrows * Dv];
__device__ __nv_bfloat16 g_Wqh[Dv * Dv], g_Wql[Dv * Dv];
__device__ __nv_bfloat16 g_Wkh[Dv * Dv], g_Wkl[Dv * Dv];
__device__ __nv_bfloat16 g_Wvh[Dv * Dv], g_Wvl[Dv * Dv];
__device__ __nv_bfloat16 g_Woh[Dv * Dv], g_Wol[Dv * Dv];
__device__ __half        g_Qh[Mrows * Dv], g_Kh[Mrows * Dv];
__device__ __half        g_Vh[Mrows * Dv], g_Vl[Mrows * Dv];
__device__ __nv_bfloat16 g_Oh[Mrows * Dv], g_Ol[Mrows * Dv];
__device__ float         g_qn[Bv * Hv * Nv], g_kn[Bv * Hv * Nv];

// ---------------------------------------------------------------------------
// Helpers (plain-sm_100-safe PTX only)
// ---------------------------------------------------------------------------
__device__ __forceinline__ uint32_t smem_u32(const void* p) {
    uint32_t a;
    asm("{ .reg .u64 t; cvta.to.shared.u64 t, %1; cvt.u32.u64 %0, t; }" : "=r"(a) : "l"(p));
    return a;
}
__device__ __forceinline__ void cp16(uint32_t dst, const void* src) {
    asm volatile("cp.async.cg.shared.global [%0], [%1], 16;" :: "r"(dst), "l"(src) : "memory");
}
#define CP_COMMIT() asm volatile("cp.async.commit_group;" ::: "memory")
#define CP_WAIT(n)  asm volatile("cp.async.wait_group %0;" :: "n"(n) : "memory")

#define LDSM4(r0, r1, r2, r3, addr) \
    asm volatile("ldmatrix.sync.aligned.m8n8.x4.shared.b16 {%0,%1,%2,%3}, [%4];" \
        : "=r"(r0), "=r"(r1), "=r"(r2), "=r"(r3) : "r"(addr))
#define LDSM4T(r0, r1, r2, r3, addr) \
    asm volatile("ldmatrix.sync.aligned.m8n8.x4.trans.shared.b16 {%0,%1,%2,%3}, [%4];" \
        : "=r"(r0), "=r"(r1), "=r"(r2), "=r"(r3) : "r"(addr))

__device__ __forceinline__ void mma_bf16(float* d, const uint32_t* a, uint32_t b0, uint32_t b1) {
    asm volatile("mma.sync.aligned.m16n8k16.row.col.f32.bf16.bf16.f32 "
        "{%0,%1,%2,%3}, {%4,%5,%6,%7}, {%8,%9}, {%0,%1,%2,%3};"
        : "+f"(d[0]), "+f"(d[1]), "+f"(d[2]), "+f"(d[3])
        : "r"(a[0]), "r"(a[1]), "r"(a[2]), "r"(a[3]), "r"(b0), "r"(b1));
}
__device__ __forceinline__ void mma_f16(float* d, const uint32_t* a, uint32_t b0, uint32_t b1) {
    asm volatile("mma.sync.aligned.m16n8k16.row.col.f32.f16.f16.f32 "
        "{%0,%1,%2,%3}, {%4,%5,%6,%7}, {%8,%9}, {%0,%1,%2,%3};"
        : "+f"(d[0]), "+f"(d[1]), "+f"(d[2]), "+f"(d[3])
        : "r"(a[0]), "r"(a[1]), "r"(a[2]), "r"(a[3]), "r"(b0), "r"(b1));
}

__device__ __forceinline__ uint32_t pack_h2(float lo, float hi) {
    __half2 h = __floats2half2_rn(lo, hi);
    return *(uint32_t*)&h;
}
__device__ __forceinline__ void bfsplit2(float a, float b, uint32_t& h, uint32_t& l) {
    asm("cvt.rn.bf16x2.f32 %0, %1, %2;" : "=r"(h) : "f"(b), "f"(a));
    float al = a - __uint_as_float(h << 16);
    float bl = b - __uint_as_float(h & 0xffff0000u);
    asm("cvt.rn.bf16x2.f32 %0, %1, %2;" : "=r"(l) : "f"(bl), "f"(al));
}

__device__ __forceinline__ float f_lg2(float x) { float r; asm("lg2.approx.f32 %0, %1;" : "=f"(r) : "f"(x)); return r; }
__device__ __forceinline__ float f_ex2(float x) { float r; asm("ex2.approx.f32 %0, %1;" : "=f"(r) : "f"(x)); return r; }
__device__ __forceinline__ float f_sqrt(float x){ float r; asm("sqrt.approx.f32 %0, %1;" : "=f"(r) : "f"(x)); return r; }

// ---------------------------------------------------------------------------
// Prep: split fp32 sources into bf16 hi/lo arrays (one pass)
// ---------------------------------------------------------------------------
__global__ void prep_split(const float* __restrict__ x, const float* __restrict__ Wq,
                           const float* __restrict__ Wk, const float* __restrict__ Wv,
                           const float* __restrict__ Wo) {
    const float* src; __nv_bfloat16 *hi, *lo; int n;
    switch (blockIdx.z) {
        case 0:  src = x;  hi = g_xh;  lo = g_xl;  n = Mrows * Dv; break;
        case 1:  src = Wq; hi = g_Wqh; lo = g_Wql; n = Dv * Dv;    break;
        case 2:  src = Wk; hi = g_Wkh; lo = g_Wkl; n = Dv * Dv;    break;
        case 3:  src = Wv; hi = g_Wvh; lo = g_Wvl; n = Dv * Dv;    break;
        default: src = Wo; hi = g_Woh; lo = g_Wol; n = Dv * Dv;    break;
    }
    int i = (blockIdx.x * 256 + threadIdx.x) * 4;
    if (i >= n) return;
    float4 v = *(const float4*)(src + i);
    uint32_t h01, l01, h23, l23;
    bfsplit2(v.x, v.y, h01, l01);
    bfsplit2(v.z, v.w, h23, l23);
    *(uint32_t*)(hi + i) = h01; *(uint32_t*)(hi + i + 2) = h23;
    *(uint32_t*)(lo + i) = l01; *(uint32_t*)(lo + i + 2) = l23;
}

// ---------------------------------------------------------------------------
// 3xBF16 GEMM, cp.async double-buffered, K-chunk 32 (8KB/tile, SW64 swizzle).
// Stage = Ah|Al|Wh|Wl x 8KB = 32KB; 2 stages = 64KB -> 2 CTAs/SM, 16 warps.
// ---------------------------------------------------------------------------
#define GSTAGE    32768
#define GEMM_SMEM (2 * GSTAGE)

__device__ __forceinline__ void gemm_cp_body(
    const __nv_bfloat16* __restrict__ Ah, const __nv_bfloat16* __restrict__ Al,
    const __nv_bfloat16* __restrict__ Wh, const __nv_bfloat16* __restrict__ Wl,
    int mode, __half* outH, __half* outL, float* fout, float* nrm_out)
{
    extern __shared__ char smem[];
    const uint32_t SB = smem_u32(smem);
    const int t = threadIdx.x, L = t & 31, wid = t >> 5;
    const int wm = wid >> 2, wn = wid & 3;
    const int m0 = blockIdx.y * 128, n0 = blockIdx.x * 128;

    // stage one K-chunk of 32 (64B rows, swizzle: ch ^= (r>>1)&3)
    auto issue = [&](int kc) {
        const int k0 = kc * 32;
        const uint32_t sbase = SB + (uint32_t)(kc & 1) * GSTAGE;
#pragma unroll
        for (int u = 0; u < 8; u++) {
            int idx = t + 256 * u;
            int tile = idx >> 9, r = (idx >> 2) & 127, ch = idx & 3;
            const __nv_bfloat16* base = (tile == 0) ? Ah : (tile == 1) ? Al : (tile == 2) ? Wh : Wl;
            int grow = ((tile < 2) ? m0 : n0) + r;
            const void* src = base + (size_t)grow * 1024 + k0 + ch * 8;
            cp16(sbase + tile * 8192 + r * 64 + (((ch ^ ((r >> 1) & 3)) << 4)), src);
        }
        CP_COMMIT();
    };

    issue(0);
    issue(1);

    // ldmatrix geometry (64B rows): addr = row*64 + ((ch ^ ((row>>1)&3))<<4)
    const int arow = wm * 64 + (L & 15);
    const int brow = wn * 32 + ((L >> 4) & 1) * 8 + (L & 7);
    const uint32_t aRowOff = (uint32_t)(arow * 64);
    const uint32_t bRowOff = (uint32_t)(16384 + brow * 64);   // Wh at +16KB
    const uint32_t aXr = (uint32_t)((arow >> 1) & 3);
    const uint32_t bXr = (uint32_t)((brow >> 1) & 3);

    float acc[4][4][4];
#pragma unroll
    for (int i = 0; i < 4; i++)
#pragma unroll
        for (int j = 0; j < 4; j++)
#pragma unroll
            for (int r = 0; r < 4; r++) acc[i][j][r] = 0.0f;

#pragma unroll 1
    for (int kc = 0; kc < 32; kc++) {
        if (kc < 31) { CP_WAIT(1); } else { CP_WAIT(0); }
        __syncthreads();
        const uint32_t sb = SB + (uint32_t)(kc & 1) * GSTAGE;
#pragma unroll
        for (int js = 0; js < 2; js++) {
            const uint32_t achunk = (uint32_t)((((2 * js + (L >> 4)) ^ aXr) << 4));
            const uint32_t bchunk = (uint32_t)((((2 * js + ((L >> 3) & 1)) ^ bXr) << 4));
            uint32_t ah[4][4], al[4][4];
#pragma unroll
            for (int i = 0; i < 4; i++) {
                LDSM4(ah[i][0], ah[i][1], ah[i][2], ah[i][3], sb + aRowOff + i * 1024 + achunk);
                LDSM4(al[i][0], al[i][1], al[i][2], al[i][3], sb + 8192 + aRowOff + i * 1024 + achunk);
            }
#pragma unroll
            for (int jp = 0; jp < 2; jp++) {
                uint32_t bh[4], bl[4];
                LDSM4(bh[0], bh[1], bh[2], bh[3], sb + bRowOff + jp * 1024 + bchunk);
                LDSM4(bl[0], bl[1], bl[2], bl[3], sb + 8192 + bRowOff + jp * 1024 + bchunk);
#pragma unroll
                for (int i = 0; i < 4; i++) {
                    mma_bf16(acc[i][jp * 2],     ah[i], bh[0], bh[1]);
                    mma_bf16(acc[i][jp * 2],     ah[i], bl[0], bl[1]);
                    mma_bf16(acc[i][jp * 2],     al[i], bh[0], bh[1]);
                    mma_bf16(acc[i][jp * 2 + 1], ah[i], bh[2], bh[3]);
                    mma_bf16(acc[i][jp * 2 + 1], ah[i], bl[2], bl[3]);
                    mma_bf16(acc[i][jp * 2 + 1], al[i], bh[2], bh[3]);
                }
            }
        }
        __syncthreads();
        if (kc + 2 < 32) issue(kc + 2);
    }

    // ---- epilogues ----
    const int rb = m0 + wm * 64 + (L >> 2);
    const int cb = n0 + wn * 32 + (L & 3) * 2;

    if (mode <= 1) {                 // Q or K: fp16 out + exact fp32 norms
        float p0s[4], p1s[4];
#pragma unroll
        for (int i = 0; i < 4; i++) {
            float s0 = 0.0f, s1 = 0.0f;
#pragma unroll
            for (int j = 0; j < 4; j++) {
                const int r = rb + i * 16, c = cb + j * 8;
                *(__half2*)(outH + (size_t)r * 1024 + c)       = __floats2half2_rn(acc[i][j][0], acc[i][j][1]);
                *(__half2*)(outH + (size_t)(r + 8) * 1024 + c) = __floats2half2_rn(acc[i][j][2], acc[i][j][3]);
                s0 = fmaf(acc[i][j][0], acc[i][j][0], fmaf(acc[i][j][1], acc[i][j][1], s0));
                s1 = fmaf(acc[i][j][2], acc[i][j][2], fmaf(acc[i][j][3], acc[i][j][3], s1));
            }
            s0 += __shfl_xor_sync(0xffffffffu, s0, 1);
            s0 += __shfl_xor_sync(0xffffffffu, s0, 2);
            s1 += __shfl_xor_sync(0xffffffffu, s1, 1);
            s1 += __shfl_xor_sync(0xffffffffu, s1, 2);
            p0s[i] = s0; p1s[i] = s1;
        }
        __syncthreads();
        float* part = (float*)smem;            // [128][4]
        if ((L & 3) == 0) {
#pragma unroll
            for (int i = 0; i < 4; i++) {
                int r0 = wm * 64 + (L >> 2) + i * 16;
                part[r0 * 4 + wn] = p0s[i];
                part[(r0 + 8) * 4 + wn] = p1s[i];
            }
        }
        __syncthreads();
        {
            int row = t >> 1, ph = t & 1;
            float s = part[row * 4 + 2 * ph] + part[row * 4 + 2 * ph + 1];
            int grow = m0 + row, head = (n0 >> 6) + ph;
            int b = grow >> 11, n = grow & 2047;
            nrm_out[((b << 4) + head) * Nv + n] = s;
        }
    } else if (mode == 2) {          // V: fp16 hi/lo
#pragma unroll
        for (int i = 0; i < 4; i++)
#pragma unroll
            for (int j = 0; j < 4; j++) {
                const int r = rb + i * 16, c = cb + j * 8;
                __half2 h0 = __floats2half2_rn(acc[i][j][0], acc[i][j][1]);
                __half2 h1 = __floats2half2_rn(acc[i][j][2], acc[i][j][3]);
                float2 f0 = __half22float2(h0), f1 = __half22float2(h1);
                __half2 l0 = __floats2half2_rn(acc[i][j][0] - f0.x, acc[i][j][1] - f0.y);
                __half2 l1 = __floats2half2_rn(acc[i][j][2] - f1.x, acc[i][j][3] - f1.y);
                *(__half2*)(outH + (size_t)r * 1024 + c)       = h0;
                *(__half2*)(outH + (size_t)(r + 8) * 1024 + c) = h1;
                *(__half2*)(outL + (size_t)r * 1024 + c)       = l0;
                *(__half2*)(outL + (size_t)(r + 8) * 1024 + c) = l1;
            }
    } else {                         // fp32 final output
#pragma unroll
        for (int i = 0; i < 4; i++)
#pragma unroll
            for (int j = 0; j < 4; j++) {
                const int r = rb + i * 16, cx = cb + j * 8;
                *(float2*)(fout + (size_t)r * 1024 + cx)       = make_float2(acc[i][j][0], acc[i][j][1]);
                *(float2*)(fout + (size_t)(r + 8) * 1024 + cx) = make_float2(acc[i][j][2], acc[i][j][3]);
            }
    }
}

__global__ __launch_bounds__(256, 2)
void proj_qkv_cp() {
    if (blockIdx.z == 0)
        gemm_cp_body(g_xh, g_xl, g_Wqh, g_Wql, 0, g_Qh, nullptr, nullptr, g_qn);
    else if (blockIdx.z == 1)
        gemm_cp_body(g_xh, g_xl, g_Wkh, g_Wkl, 1, g_Kh, nullptr, nullptr, g_kn);
    else
        gemm_cp_body(g_xh, g_xl, g_Wvh, g_Wvl, 2, g_Vh, g_Vl, nullptr, nullptr);
}

__global__ __launch_bounds__(256, 2)
void out_proj_cp(float* __restrict__ out) {
    gemm_cp_body(g_Oh, g_Ol, g_Woh, g_Wol, 3, nullptr, nullptr, out, nullptr);
}

// ---------------------------------------------------------------------------
// Hyperbolic flash attention (R5-proven, unchanged)
// ---------------------------------------------------------------------------
#define AST0  16384
#define ASTSZ 24576
#define AKN   (16384 + 2 * ASTSZ)
#define ASMEM (AKN + 2 * 256)

__global__ __launch_bounds__(256, 2)
void attn_cp(const float* __restrict__ lc_p, const float* __restrict__ lb_p) {
    extern __shared__ char smem[];
    const uint32_t SB = smem_u32(smem);
    const uint32_t QS = SB;

    const int t = threadIdx.x;
    const int L = t & 31;
    const int w = t >> 5;
    const int bh = blockIdx.y;
    const int b  = bh >> 4, h = bh & 15;
    const int qx = (int)gridDim.x - 1 - (int)blockIdx.x;
    const int qrow0 = qx * 128;
    const int wr0 = qrow0 + w * 16;

    const float cc = log1pf(expf(*lc_p));
    const float bb = log1pf(expf(*lb_p)) + 0.5f;
    const float bL2E = bb * 1.4426950408889634f;
    const float C0 = -bL2E * 0.693f;
    const float C1 = -bL2E * 0.34657359f;
    const float C2 = -bL2E * cc * 0.25f;

    const int n_kt = 2 * qx + 2;

    auto issueKV = [&](int kt) {
        const int k0 = kt * 64;
        const uint32_t sb = SB + AST0 + (uint32_t)(kt & 1) * ASTSZ;
#pragma unroll
        for (int u = 0; u < 6; u++) {
            int idx = t + 256 * u;
            int tile = idx >> 9, r = (idx >> 3) & 63, ch = idx & 7;
            const __half* base = (tile == 0) ? g_Kh : (tile == 1) ? g_Vh : g_Vl;
            const void* src = base + (size_t)(b * Nv + k0 + r) * Dv + h * Dhv + ch * 8;
            cp16(sb + tile * 8192 + r * 128 + ((ch ^ (r & 7)) << 4), src);
        }
        if (t < 16)
            cp16(SB + AKN + (kt & 1) * 256 + t * 16, g_kn + (size_t)bh * Nv + k0 + t * 4);
        CP_COMMIT();
    };

#pragma unroll
    for (int u = 0; u < 4; u++) {
        int idx = t + 256 * u;
        int r = idx >> 3, ch = idx & 7;
        const void* src = g_Qh + (size_t)(b * Nv + qrow0 + r) * Dv + h * Dhv + ch * 8;
        cp16(QS + r * 128 + ((ch ^ (r & 7)) << 4), src);
    }
    issueKV(0);
    if (n_kt > 1) issueKV(1);

    const float qn0 = g_qn[(size_t)bh * Nv + wr0 + (L >> 2)];
    const float qn1 = g_qn[(size_t)bh * Nv + wr0 + (L >> 2) + 8];

    float o[8][4];
#pragma unroll
    for (int j = 0; j < 8; j++)
#pragma unroll
        for (int e = 0; e < 4; e++) o[j][e] = 0.0f;
    float m0r = -1e30f, m1r = -1e30f, l0r = 0.0f, l1r = 0.0f;

#pragma unroll 1
    for (int kt = 0; kt < n_kt; kt++) {
        if (kt + 1 < n_kt) { CP_WAIT(1); } else { CP_WAIT(0); }
        __syncthreads();
        const int k0 = kt * 64;
        const uint32_t sb = SB + AST0 + (uint32_t)(kt & 1) * ASTSZ;
        const float* kn_s = (const float*)(smem + AKN + (kt & 1) * 256);

        if (k0 <= wr0 + 15) {
            float sc[8][4];
#pragma unroll
            for (int j = 0; j < 8; j++)
#pragma unroll
                for (int e = 0; e < 4; e++) sc[j][e] = 0.0f;
#pragma unroll
            for (int ks = 0; ks < 4; ks++) {
                uint32_t aq[4];
                {
                    int arow = w * 16 + (L & 15);
                    int ch = 2 * ks + (L >> 4);
                    LDSM4(aq[0], aq[1], aq[2], aq[3], QS + arow * 128 + ((ch ^ (arow & 7)) << 4));
                }
#pragma unroll
                for (int jn = 0; jn < 4; jn++) {
                    uint32_t bk[4];
                    int brow = jn * 16 + ((L >> 4) & 1) * 8 + (L & 7);
                    int ch = 2 * ks + ((L >> 3) & 1);
                    LDSM4(bk[0], bk[1], bk[2], bk[3], sb + brow * 128 + ((ch ^ (brow & 7)) << 4));
                    mma_f16(sc[2 * jn],     aq, bk[0], bk[1]);
                    mma_f16(sc[2 * jn + 1], aq, bk[2], bk[3]);
                }
            }

            const bool need_mask = (k0 + 63 > wr0);
            const int rg0 = wr0 + (L >> 2), rg1 = rg0 + 8;
            float vm0 = -1e30f, vm1 = -1e30f;
#pragma unroll
            for (int j = 0; j < 8; j++) {
                float2 kn2 = *(const float2*)(kn_s + 8 * j + 2 * (L & 3));
                const int cg = k0 + 8 * j + 2 * (L & 3);
#pragma unroll
                for (int e = 0; e < 4; e++) {
                    float qn = (e < 2) ? qn0 : qn1;
                    float kn = (e & 1) ? kn2.y : kn2.x;
                    float ns = qn + kn;
                    float da = fmaxf(fmaf(-2.0f, sc[j][e], ns), 0.0f) + 1e-8f;
                    float s2;
                    if (da > 4.0f) {
                        s2 = fmaf(C1, f_lg2(da), fmaf(C2, ns, C0));
                    } else {
                        float ed = f_sqrt(da);
                        float dist;
                        if (ed < 0.1f) {
                            float cn = cc * ns;
                            dist = ed * (1.0f + 0.5f * cn + 0.125f * cn * cn);
                        } else if (ed > 2.0f) {
                            dist = 0.693f + 0.6931472f * f_lg2(ed + 1e-8f) + cc * ns * 0.25f;
                        } else {
                            dist = ed * f_sqrt(1.0f + cc * ns);
                        }
                        s2 = -bL2E * dist;
                    }
                    if (need_mask) {
                        int rowg = (e < 2) ? rg0 : rg1;
                        if (cg + (e & 1) > rowg) s2 = -1e30f;
                    }
                    sc[j][e] = s2;
                    if (e < 2) vm0 = fmaxf(vm0, s2); else vm1 = fmaxf(vm1, s2);
                }
            }
            vm0 = fmaxf(vm0, __shfl_xor_sync(0xffffffffu, vm0, 1));
            vm0 = fmaxf(vm0, __shfl_xor_sync(0xffffffffu, vm0, 2));
            vm1 = fmaxf(vm1, __shfl_xor_sync(0xffffffffu, vm1, 1));
            vm1 = fmaxf(vm1, __shfl_xor_sync(0xffffffffu, vm1, 2));

            float mn0 = fmaxf(m0r, vm0), mn1 = fmaxf(m1r, vm1);
            float corr0 = f_ex2(m0r - mn0), corr1 = f_ex2(m1r - mn1);
            m0r = mn0; m1r = mn1;

            float rs0 = 0.0f, rs1 = 0.0f;
#pragma unroll
            for (int j = 0; j < 8; j++) {
                float p0 = f_ex2(sc[j][0] - mn0);
                float p1 = f_ex2(sc[j][1] - mn0);
                float p2 = f_ex2(sc[j][2] - mn1);
                float p3 = f_ex2(sc[j][3] - mn1);
                sc[j][0] = p0; sc[j][1] = p1; sc[j][2] = p2; sc[j][3] = p3;
                rs0 += p0 + p1; rs1 += p2 + p3;
            }
            rs0 += __shfl_xor_sync(0xffffffffu, rs0, 1);
            rs0 += __shfl_xor_sync(0xffffffffu, rs0, 2);
            rs1 += __shfl_xor_sync(0xffffffffu, rs1, 1);
            rs1 += __shfl_xor_sync(0xffffffffu, rs1, 2);
            l0r = l0r * corr0 + rs0;
            l1r = l1r * corr1 + rs1;
#pragma unroll
            for (int j = 0; j < 8; j++) {
                o[j][0] *= corr0; o[j][1] *= corr0;
                o[j][2] *= corr1; o[j][3] *= corr1;
            }

#pragma unroll
            for (int ks = 0; ks < 4; ks++) {
                const int j0 = 2 * ks, j1 = 2 * ks + 1;
                uint32_t aph[4], apl[4];
                {
                    uint32_t h0 = pack_h2(sc[j0][0], sc[j0][1]);
                    uint32_t h1 = pack_h2(sc[j0][2], sc[j0][3]);
                    uint32_t h2 = pack_h2(sc[j1][0], sc[j1][1]);
                    uint32_t h3 = pack_h2(sc[j1][2], sc[j1][3]);
                    aph[0] = h0; aph[1] = h1; aph[2] = h2; aph[3] = h3;
                    float2 b0 = __half22float2(*(__half2*)&h0);
                    float2 b1 = __half22float2(*(__half2*)&h1);
                    float2 b2 = __half22float2(*(__half2*)&h2);
                    float2 b3 = __half22float2(*(__half2*)&h3);
                    apl[0] = pack_h2(sc[j0][0] - b0.x, sc[j0][1] - b0.y);
                    apl[1] = pack_h2(sc[j0][2] - b1.x, sc[j0][3] - b1.y);
                    apl[2] = pack_h2(sc[j1][0] - b2.x, sc[j1][1] - b2.y);
                    apl[3] = pack_h2(sc[j1][2] - b3.x, sc[j1][3] - b3.y);
                }
                const int krow = 16 * ks + (L & 15);
#pragma unroll
                for (int jd = 0; jd < 4; jd++) {
                    int ch = 2 * jd + (L >> 4);
                    uint32_t voff = (uint32_t)(krow * 128 + ((ch ^ (krow & 7)) << 4));
                    uint32_t vhf[4], vlf[4];
                    LDSM4T(vhf[0], vhf[1], vhf[2], vhf[3], sb + 8192 + voff);
                    LDSM4T(vlf[0], vlf[1], vlf[2], vlf[3], sb + 16384 + voff);
                    mma_f16(o[2 * jd],     aph, vhf[0], vhf[1]);
                    mma_f16(o[2 * jd],     apl, vhf[0], vhf[1]);
                    mma_f16(o[2 * jd],     aph, vlf[0], vlf[1]);
                    mma_f16(o[2 * jd + 1], aph, vhf[2], vhf[3]);
                    mma_f16(o[2 * jd + 1], apl, vhf[2], vhf[3]);
                    mma_f16(o[2 * jd + 1], aph, vlf[2], vlf[3]);
                }
            }
        }
        __syncthreads();
        if (kt + 2 < n_kt) issueKV(kt + 2);
    }

    const float inv0 = 1.0f / l0r, inv1 = 1.0f / l1r;
    const size_t base0 = (size_t)(b * Nv + wr0 + (L >> 2)) * Dv + h * Dhv + 2 * (L & 3);
    const size_t base1 = base0 + 8 * (size_t)Dv;
#pragma unroll
    for (int j = 0; j < 8; j++) {
        uint32_t hh, ll;
        bfsplit2(o[j][0] * inv0, o[j][1] * inv0, hh, ll);
        *(uint32_t*)(g_Oh + base0 + 8 * j) = hh;
        *(uint32_t*)(g_Ol + base0 + 8 * j) = ll;
        bfsplit2(o[j][2] * inv1, o[j][3] * inv1, hh, ll);
        *(uint32_t*)(g_Oh + base1 + 8 * j) = hh;
        *(uint32_t*)(g_Ol + base1 + 8 * j) = ll;
    }
}

// ---------------------------------------------------------------------------
// Launch
// ---------------------------------------------------------------------------
extern "C" void kernel_launch(void* const* d_in, const int* in_sizes, int n_in,
                              void* d_out, int out_size) {
    const float* x  = (const float*)d_in[0];
    const float* Wq = (const float*)d_in[1];
    const float* Wk = (const float*)d_in[2];
    const float* Wv = (const float*)d_in[3];
    const float* Wo = (const float*)d_in[4];
    const float* lc = (const float*)d_in[5];
    const float* lb = (const float*)d_in[6];
    float* out = (float*)d_out;

    cudaFuncSetAttribute(proj_qkv_cp, cudaFuncAttributeMaxDynamicSharedMemorySize, GEMM_SMEM);
    cudaFuncSetAttribute(out_proj_cp, cudaFuncAttributeMaxDynamicSharedMemorySize, GEMM_SMEM);
    cudaFuncSetAttribute(attn_cp,     cudaFuncAttributeMaxDynamicSharedMemorySize, ASMEM);

    prep_split<<<dim3(4096, 1, 5), 256>>>(x, Wq, Wk, Wv, Wo);
    proj_qkv_cp<<<dim3(8, 32, 3), 256, GEMM_SMEM>>>();
    attn_cp<<<dim3(Nv / 128, Bv * Hv), 256, ASMEM>>>(lc, lb);
    out_proj_cp<<<dim3(8, 32), 256, GEMM_SMEM>>>(out);
}